// round 2
// baseline (speedup 1.0000x reference)
#include <cuda_runtime.h>

// ---------------- problem constants ----------------
#define BATCH 512
#define EDIM  128
#define NCOLS 640          // 2E (user) + 3E (item)
#define EPS   1e-5f

// split-K configuration: slices proportional to K, 4 row-tiles each
// gemms: 0=kw(K=372226) 1=following(19065) 2=author(19065) 3=magazine(28028) 4=tag(86037)
#define NSL_KW 64
#define NSL_FO 4
#define NSL_AU 4
#define NSL_MG 5
#define NSL_TG 15
#define NSL_TOT (NSL_KW + NSL_FO + NSL_AU + NSL_MG + NSL_TG)   // 92

// ---------------- device scratch ----------------
__device__ float g_part[(long)NSL_TOT * BATCH * EDIM];   // 24 MB split-K partials
__device__ float g_emb[BATCH * NCOLS];                   // [B, 640] embeddings
__device__ float g_scale[NCOLS];
__device__ float g_shift[NCOLS];
__device__ float g_hu[BATCH * EDIM];
__device__ float g_ue[BATCH * EDIM];
__device__ float g_hi[BATCH * EDIM];
__device__ float g_ie[BATCH * EDIM];

// ---------------- packed f32x2 helpers ----------------
#define FMA_F32X2(d, a, b, c) \
    asm("fma.rn.f32x2 %0, %1, %2, %3;" : "=l"(d) : "l"(a), "l"(b), "l"(c))
#define PACK_DUP_F32X2(out, x) \
    asm("mov.b64 %0, {%1, %1};" : "=l"(out) : "r"(__float_as_uint(x)))

struct BigParams {
    const float* A[5];
    const float* W[5];
    int K[5];
    int kc[5];          // K per slice
    int cum[6];         // cumulative slice counts
};

struct RedParams {
    const float* bias[5];
    int cum[6];
    int col_ofs[5];
};

// ================= big split-K GEMM: 128x128 tile, fp32 via f32x2 =================
__global__ __launch_bounds__(256, 2) void big_gemm_kernel(BigParams p) {
    int bid    = blockIdx.x;
    int sidx   = bid >> 2;        // global slice index
    int tile_i = bid & 3;         // row tile (B/128 = 4)

    int g = 0;
    while (sidx >= p.cum[g + 1]) g++;
    int s  = sidx - p.cum[g];
    const float* A = p.A[g];
    const float* W = p.W[g];
    int K  = p.K[g];
    int k0 = s * p.kc[g];
    int k1 = min(k0 + p.kc[g], K);
    int m0 = tile_i * 128;

    __shared__ float As[8][128];
    __shared__ float Bs[8][128];

    int t  = threadIdx.x;
    int tx = t & 15;      // 16 col groups of 8
    int ty = t >> 4;      // 16 row groups of 8

    unsigned long long acc2[8][4];
    #pragma unroll
    for (int i = 0; i < 8; i++)
        #pragma unroll
        for (int j = 0; j < 4; j++) acc2[i][j] = 0ULL;

    for (int kb = k0; kb < k1; kb += 8) {
        #pragma unroll
        for (int r = 0; r < 4; r++) {
            int e = t + 256 * r;
            int m = e >> 3, kk = e & 7;
            int k = kb + kk;
            As[kk][m] = (k < k1) ? A[(long)(m0 + m) * K + k] : 0.f;
        }
        #pragma unroll
        for (int r = 0; r < 4; r++) {
            int e = t + 256 * r;
            int n = e >> 3, kk = e & 7;
            int k = kb + kk;
            Bs[kk][n] = (k < k1) ? W[(long)n * K + k] : 0.f;
        }
        __syncthreads();

        #pragma unroll
        for (int kk = 0; kk < 8; kk++) {
            float4 a0 = *(const float4*)&As[kk][ty * 8];
            float4 a1 = *(const float4*)&As[kk][ty * 8 + 4];
            // b pairs come packed straight from shared memory
            unsigned long long b2[4];
            ulonglong2 bl0 = *(const ulonglong2*)&Bs[kk][tx * 8];
            ulonglong2 bl1 = *(const ulonglong2*)&Bs[kk][tx * 8 + 4];
            b2[0] = bl0.x; b2[1] = bl0.y; b2[2] = bl1.x; b2[3] = bl1.y;

            float av[8] = {a0.x, a0.y, a0.z, a0.w, a1.x, a1.y, a1.z, a1.w};
            #pragma unroll
            for (int i = 0; i < 8; i++) {
                unsigned long long a2;
                PACK_DUP_F32X2(a2, av[i]);
                #pragma unroll
                for (int j = 0; j < 4; j++)
                    FMA_F32X2(acc2[i][j], a2, b2[j], acc2[i][j]);
            }
        }
        __syncthreads();
    }

    float* out = g_part + (long)sidx * (BATCH * EDIM);
    #pragma unroll
    for (int i = 0; i < 8; i++) {
        int m = m0 + ty * 8 + i;
        #pragma unroll
        for (int j = 0; j < 4; j++) {
            float2 v = *(float2*)&acc2[i][j];
            *(float2*)&out[(long)m * EDIM + tx * 8 + j * 2] = v;
        }
    }
}

// ================= reduce split-K partials + bias into g_emb =================
__global__ void reduce_kernel(RedParams p) {
    int g   = blockIdx.y;
    int idx = blockIdx.x * blockDim.x + threadIdx.x;   // 0..65535
    int b   = idx >> 7;
    int j   = idx & 127;
    float v = p.bias[g][j];
    int s0 = p.cum[g], s1 = p.cum[g + 1];
    for (int s = s0; s < s1; s++)
        v += g_part[(long)s * (BATCH * EDIM) + idx];
    g_emb[b * NCOLS + p.col_ofs[g] + j] = v;
}

// ================= per-column BN stats -> scale/shift =================
__global__ void stats_kernel(const float* g_u, const float* be_u,
                             const float* g_i, const float* be_i) {
    int c   = blockIdx.x;         // 0..639
    int tid = threadIdx.x;        // 256 threads
    __shared__ float ssum[256], ssq[256];
    float s = 0.f, q = 0.f;
    for (int b = tid; b < BATCH; b += 256) {
        float x = g_emb[b * NCOLS + c];
        s += x; q += x * x;
    }
    ssum[tid] = s; ssq[tid] = q;
    __syncthreads();
    for (int ofs = 128; ofs > 0; ofs >>= 1) {
        if (tid < ofs) { ssum[tid] += ssum[tid + ofs]; ssq[tid] += ssq[tid + ofs]; }
        __syncthreads();
    }
    if (tid == 0) {
        float mean = ssum[0] * (1.f / BATCH);
        float var  = ssq[0] * (1.f / BATCH) - mean * mean;
        float gamma = (c < 256) ? g_u[c]  : g_i[c - 256];
        float beta  = (c < 256) ? be_u[c] : be_i[c - 256];
        float sc = gamma * rsqrtf(var + EPS);
        g_scale[c] = sc;
        g_shift[c] = beta - mean * sc;
    }
}

// ================= small tower GEMM: C = act((A*scale+shift) @ W^T + bias) =================
// BM=32, BN=128, BK=16. a_sel: 0=g_emb(+a_ofs), 1=g_hu, 2=g_hi. c_sel: 0..3 -> hu/ue/hi/ie
__global__ __launch_bounds__(256) void small_gemm_kernel(
    int a_sel, int a_ofs, int K,
    const float* __restrict__ W, const float* __restrict__ bias,
    int use_norm, int do_relu, int c_sel) {

    const float* A; int lda;
    if (a_sel == 0)      { A = g_emb + a_ofs; lda = NCOLS; }
    else if (a_sel == 1) { A = g_hu;          lda = EDIM;  }
    else                 { A = g_hi;          lda = EDIM;  }
    float* C = (c_sel == 0) ? g_hu : (c_sel == 1) ? g_ue
             : (c_sel == 2) ? g_hi : g_ie;

    __shared__ float As[16][32];
    __shared__ float Ws[16][128];

    int t  = threadIdx.x;
    int m0 = blockIdx.x * 32;
    int tx = t & 31;     // 32 col groups of 4
    int ty = t >> 5;     // 8 row groups of 4

    float acc[4][4];
    #pragma unroll
    for (int i = 0; i < 4; i++)
        #pragma unroll
        for (int j = 0; j < 4; j++) acc[i][j] = 0.f;

    for (int kb = 0; kb < K; kb += 16) {
        #pragma unroll
        for (int r = 0; r < 2; r++) {
            int e = t + 256 * r;
            int m = e >> 4, kk = e & 15;
            int c = kb + kk;
            float v = A[(m0 + m) * lda + c];
            if (use_norm) v = v * g_scale[a_ofs + c] + g_shift[a_ofs + c];
            As[kk][m] = v;
        }
        #pragma unroll
        for (int r = 0; r < 8; r++) {
            int e = t + 256 * r;
            int j = e >> 4, kk = e & 15;
            Ws[kk][j] = W[j * K + kb + kk];
        }
        __syncthreads();
        #pragma unroll
        for (int kk = 0; kk < 16; kk++) {
            float4 a = *(const float4*)&As[kk][ty * 4];
            float4 b = *(const float4*)&Ws[kk][tx * 4];
            float av[4] = {a.x, a.y, a.z, a.w};
            float bv[4] = {b.x, b.y, b.z, b.w};
            #pragma unroll
            for (int i = 0; i < 4; i++)
                #pragma unroll
                for (int j = 0; j < 4; j++) acc[i][j] += av[i] * bv[j];
        }
        __syncthreads();
    }

    #pragma unroll
    for (int i = 0; i < 4; i++) {
        int m = m0 + ty * 4 + i;
        float4 v;
        float* vp = &v.x;
        #pragma unroll
        for (int j = 0; j < 4; j++) {
            float x = acc[i][j] + bias[tx * 4 + j];
            if (do_relu) x = fmaxf(x, 0.f);
            vp[j] = x;
        }
        *(float4*)&C[m * EDIM + tx * 4] = v;
    }
}

// ================= final dot product =================
__global__ void dot_kernel(float* __restrict__ out) {
    int warp = threadIdx.x >> 5;
    int lane = threadIdx.x & 31;
    int b = blockIdx.x * 8 + warp;
    float s = 0.f;
    #pragma unroll
    for (int j = lane; j < EDIM; j += 32)
        s += g_ue[b * EDIM + j] * g_ie[b * EDIM + j];
    #pragma unroll
    for (int o = 16; o > 0; o >>= 1)
        s += __shfl_xor_sync(0xffffffffu, s, o);
    if (lane == 0) out[b] = s;
}

// ================= launch =================
extern "C" void kernel_launch(void* const* d_in, const int* in_sizes, int n_in,
                              void* d_out, int out_size) {
    const float* kw   = (const float*)d_in[0];
    const float* fo   = (const float*)d_in[1];
    const float* au   = (const float*)d_in[2];
    const float* mg   = (const float*)d_in[3];
    const float* tg   = (const float*)d_in[4];
    const float* W_kw = (const float*)d_in[5];
    const float* b_kw = (const float*)d_in[6];
    const float* W_au = (const float*)d_in[7];
    const float* b_au = (const float*)d_in[8];
    const float* W_mg = (const float*)d_in[9];
    const float* b_mg = (const float*)d_in[10];
    const float* W_tg = (const float*)d_in[11];
    const float* b_tg = (const float*)d_in[12];
    const float* g_u  = (const float*)d_in[13];
    const float* be_u = (const float*)d_in[14];
    const float* W_u1 = (const float*)d_in[15];
    const float* b_u1 = (const float*)d_in[16];
    const float* W_u2 = (const float*)d_in[17];
    const float* b_u2 = (const float*)d_in[18];
    const float* g_i  = (const float*)d_in[19];
    const float* be_i = (const float*)d_in[20];
    const float* W_i1 = (const float*)d_in[21];
    const float* b_i1 = (const float*)d_in[22];
    const float* W_i2 = (const float*)d_in[23];
    const float* b_i2 = (const float*)d_in[24];

    const int KW = 372226, AU = 19065, MG = 28028, TG = 86037;

    BigParams bp;
    bp.A[0] = kw;  bp.A[1] = fo;  bp.A[2] = au;  bp.A[3] = mg;  bp.A[4] = tg;
    bp.W[0] = W_kw; bp.W[1] = W_au; bp.W[2] = W_au; bp.W[3] = W_mg; bp.W[4] = W_tg;
    bp.K[0] = KW;  bp.K[1] = AU;  bp.K[2] = AU;  bp.K[3] = MG;  bp.K[4] = TG;
    bp.kc[0] = (KW + NSL_KW - 1) / NSL_KW;
    bp.kc[1] = (AU + NSL_FO - 1) / NSL_FO;
    bp.kc[2] = (AU + NSL_AU - 1) / NSL_AU;
    bp.kc[3] = (MG + NSL_MG - 1) / NSL_MG;
    bp.kc[4] = (TG + NSL_TG - 1) / NSL_TG;
    bp.cum[0] = 0;
    bp.cum[1] = NSL_KW;
    bp.cum[2] = NSL_KW + NSL_FO;
    bp.cum[3] = NSL_KW + NSL_FO + NSL_AU;
    bp.cum[4] = NSL_KW + NSL_FO + NSL_AU + NSL_MG;
    bp.cum[5] = NSL_TOT;

    RedParams rp;
    rp.bias[0] = b_kw; rp.bias[1] = b_au; rp.bias[2] = b_au;
    rp.bias[3] = b_mg; rp.bias[4] = b_tg;
    for (int i = 0; i < 6; i++) rp.cum[i] = bp.cum[i];
    rp.col_ofs[0] = 0;   rp.col_ofs[1] = 128; rp.col_ofs[2] = 256;
    rp.col_ofs[3] = 384; rp.col_ofs[4] = 512;

    big_gemm_kernel<<<NSL_TOT * 4, 256>>>(bp);
    reduce_kernel<<<dim3((BATCH * EDIM) / 256, 5), 256>>>(rp);
    stats_kernel<<<NCOLS, 256>>>(g_u, be_u, g_i, be_i);

    // user tower: h = relu(BN(emb[:,0:256]) @ W_u1^T + b_u1); ue = h @ W_u2^T + b_u2
    small_gemm_kernel<<<BATCH / 32, 256>>>(0, 0,   256, W_u1, b_u1, 1, 1, 0);
    small_gemm_kernel<<<BATCH / 32, 256>>>(1, 0,   128, W_u2, b_u2, 0, 0, 1);
    // item tower
    small_gemm_kernel<<<BATCH / 32, 256>>>(0, 256, 384, W_i1, b_i1, 1, 1, 2);
    small_gemm_kernel<<<BATCH / 32, 256>>>(2, 0,   128, W_i2, b_i2, 0, 0, 3);

    dot_kernel<<<BATCH / 8, 256>>>((float*)d_out);
}

// round 4
// speedup vs baseline: 1.3684x; 1.3684x over previous
#include <cuda_runtime.h>
#include <cstdint>

// ---------------- problem constants ----------------
#define BATCH 512
#define EDIM  128
#define NCOLS 640
#define EPS   1e-5f

// split-K: 74 slices, 2 row halves -> 148 CTAs (one wave)
#define NSL_KW 52
#define NSL_FO 3
#define NSL_AU 3
#define NSL_MG 4
#define NSL_TG 12
#define NSL_TOT (NSL_KW + NSL_FO + NSL_AU + NSL_MG + NSL_TG)   // 74

#define CH 32                 // K elements per chunk
#define STAGE 49152           // A_hi 16K | A_lo 16K | W_hi 8K | W_lo 8K
#define OFS_ALO 16384
#define OFS_WHI 32768
#define OFS_WLO 40960
#define SMEM_DYN (2 * STAGE + 128)

// ---------------- device scratch ----------------
__device__ float g_part[(long)NSL_TOT * BATCH * EDIM];   // ~19.4 MB
__device__ float g_emb[BATCH * NCOLS];
__device__ float g_scale[NCOLS];
__device__ float g_shift[NCOLS];
__device__ float g_hu[BATCH * EDIM];
__device__ float g_ue[BATCH * EDIM];
__device__ float g_hi_[BATCH * EDIM];
__device__ float g_ie[BATCH * EDIM];

// ---------------- helpers ----------------
__device__ __forceinline__ uint32_t smem_u32(const void* p) {
    uint32_t a;
    asm("{ .reg .u64 t; cvta.to.shared.u64 t, %1; cvt.u32.u64 %0, t; }" : "=r"(a) : "l"(p));
    return a;
}

// split float pair -> packed bf16x2 (hi, lo); x0 in low half
__device__ __forceinline__ void split_pair(float x0, float x1,
                                           uint32_t& hi, uint32_t& lo) {
    asm("cvt.rn.bf16x2.f32 %0, %1, %2;" : "=r"(hi) : "f"(x1), "f"(x0));
    float h0 = __uint_as_float(hi << 16);
    float h1 = __uint_as_float(hi & 0xffff0000u);
    float l0 = x0 - h0;
    float l1 = x1 - h1;
    asm("cvt.rn.bf16x2.f32 %0, %1, %2;" : "=r"(lo) : "f"(l1), "f"(l0));
}

#define LDX4(r, addr) \
    asm volatile("ldmatrix.sync.aligned.m8n8.x4.shared.b16 {%0,%1,%2,%3}, [%4];" \
        : "=r"((r)[0]), "=r"((r)[1]), "=r"((r)[2]), "=r"((r)[3]) : "r"(addr))

#define MMA16816(c, a, b) \
    asm volatile("mma.sync.aligned.m16n8k16.row.col.f32.bf16.bf16.f32 " \
        "{%0,%1,%2,%3}, {%4,%5,%6,%7}, {%8,%9}, {%0,%1,%2,%3};" \
        : "+f"((c)[0]), "+f"((c)[1]), "+f"((c)[2]), "+f"((c)[3]) \
        : "r"((a)[0]), "r"((a)[1]), "r"((a)[2]), "r"((a)[3]), \
          "r"((b)[0]), "r"((b)[1]))

struct BigParams {
    const float* A[5];
    const float* W[5];
    int K[5];
    int kc[5];
    int cum[6];
};
struct RedParams {
    const float* bias[5];
    int cum[6];
    int col_ofs[5];
};

// ================= split-bf16 mma.sync big GEMM =================
// CTA: 256 rows x one K-slice. 16 warps, warp tile 32m x 64n.
__global__ __launch_bounds__(512, 1) void big_gemm_kernel(BigParams p) {
    extern __shared__ __align__(128) char dyn_smem[];
    const uint32_t sBase = (smem_u32(dyn_smem) + 127u) & ~127u;

    const int t    = threadIdx.x;
    const int lane = t & 31;
    const int w    = t >> 5;

    const int sidx   = blockIdx.x >> 1;
    const int m_base = (blockIdx.x & 1) * 256;

    int g = 0;
    while (sidx >= p.cum[g + 1]) g++;
    const int s_loc = sidx - p.cum[g];
    const float* __restrict__ A = p.A[g];
    const float* __restrict__ W = p.W[g];
    const int K  = p.K[g];
    const int k0 = s_loc * p.kc[g];
    const int k1 = min(k0 + p.kc[g], K);
    const int nchunks = (k1 - k0 + CH - 1) / CH;
    const bool evenK = (K & 1) == 0;

    // ---- load-phase thread mapping ----
    const int kp   = lane & 15;          // k-pair 0..15
    const int rsub = lane >> 4;          // 0/1
    const int rbase = w * 2 + rsub;      // row within a 32-row pass
    const uint32_t stsCol = (uint32_t)kp * 4u;

    // ---- mma-phase warp mapping ----
    const int wm = w >> 1;               // 0..7  (m subtile of 32)
    const int wn = w & 1;                // 0..1  (n half of 64)
    const int aRow  = wm * 32 + (lane & 15);
    const uint32_t aXor = (uint32_t)((aRow & 6) << 3);
    const uint32_t aCol = (uint32_t)((lane >> 4) * 16);
    const int bRow  = wn * 64 + ((lane >> 4) & 1) * 8 + (lane & 7);
    const uint32_t bXor = (uint32_t)((bRow & 6) << 3);
    const uint32_t bCol = (uint32_t)(((lane >> 3) & 1) * 16);

    float acc[2][4][2][4];
    #pragma unroll
    for (int mi = 0; mi < 2; mi++)
        #pragma unroll
        for (int np = 0; np < 4; np++)
            #pragma unroll
            for (int nt = 0; nt < 2; nt++)
                #pragma unroll
                for (int r = 0; r < 4; r++) acc[mi][np][nt][r] = 0.f;

    uint32_t ha[8], la[8], hw[4], lw[4];

    // ---- chunk load into held regs ----
    #define LOAD_CHUNK(IDX)                                                   \
    do {                                                                      \
        const int kb = k0 + (IDX) * CH;                                       \
        const int kk = kb + 2 * kp;                                           \
        const bool full = (kb + CH <= k1);                                    \
        _Pragma("unroll")                                                     \
        for (int pp = 0; pp < 8; pp++) {                                      \
            int r = pp * 32 + rbase;                                          \
            long gi = (long)(m_base + r) * K + kk;                            \
            float x0, x1;                                                     \
            if (full && evenK) { float2 v = *(const float2*)&A[gi]; x0 = v.x; x1 = v.y; } \
            else { x0 = (kk < k1) ? A[gi] : 0.f; x1 = (kk + 1 < k1) ? A[gi + 1] : 0.f; } \
            split_pair(x0, x1, ha[pp], la[pp]);                               \
        }                                                                     \
        _Pragma("unroll")                                                     \
        for (int pp = 0; pp < 4; pp++) {                                      \
            int r = pp * 32 + rbase;                                          \
            long gi = (long)r * K + kk;                                       \
            float x0, x1;                                                     \
            if (full && evenK) { float2 v = *(const float2*)&W[gi]; x0 = v.x; x1 = v.y; } \
            else { x0 = (kk < k1) ? W[gi] : 0.f; x1 = (kk + 1 < k1) ? W[gi + 1] : 0.f; } \
            split_pair(x0, x1, hw[pp], lw[pp]);                               \
        }                                                                     \
    } while (0)

    // ---- store held regs into stage ----
    #define STS_CHUNK(SO)                                                     \
    do {                                                                      \
        const uint32_t so = sBase + (SO);                                     \
        _Pragma("unroll")                                                     \
        for (int pp = 0; pp < 8; pp++) {                                      \
            uint32_t r = (uint32_t)(pp * 32 + rbase);                         \
            uint32_t off = r * 64u + (stsCol ^ ((r & 6u) << 3));              \
            asm volatile("st.shared.b32 [%0], %1;" :: "r"(so + off), "r"(ha[pp]) : "memory"); \
            asm volatile("st.shared.b32 [%0], %1;" :: "r"(so + OFS_ALO + off), "r"(la[pp]) : "memory"); \
        }                                                                     \
        _Pragma("unroll")                                                     \
        for (int pp = 0; pp < 4; pp++) {                                      \
            uint32_t r = (uint32_t)(pp * 32 + rbase);                         \
            uint32_t off = r * 64u + (stsCol ^ ((r & 6u) << 3));              \
            asm volatile("st.shared.b32 [%0], %1;" :: "r"(so + OFS_WHI + off), "r"(hw[pp]) : "memory"); \
            asm volatile("st.shared.b32 [%0], %1;" :: "r"(so + OFS_WLO + off), "r"(lw[pp]) : "memory"); \
        }                                                                     \
    } while (0)

    // prologue: chunk 0 into stage 0
    LOAD_CHUNK(0);
    STS_CHUNK(0);
    __syncthreads();

    for (int i = 0; i < nchunks; i++) {
        const bool more = (i + 1 < nchunks);
        if (more) LOAD_CHUNK(i + 1);

        // ---- mma over stage i&1 ----
        {
            const uint32_t so = sBase + (uint32_t)(i & 1) * STAGE;
            #pragma unroll
            for (int ks = 0; ks < 2; ks++) {
                const uint32_t colA = ((uint32_t)(ks * 32) + aCol) ^ aXor;
                const uint32_t colB = ((uint32_t)(ks * 32) + bCol) ^ bXor;
                uint32_t AH[2][4], AL[2][4];
                #pragma unroll
                for (int mi = 0; mi < 2; mi++) {
                    uint32_t ra = so + (uint32_t)(aRow + mi * 16) * 64u + colA;
                    LDX4(AH[mi], ra);
                    LDX4(AL[mi], ra + OFS_ALO);
                }
                #pragma unroll
                for (int np = 0; np < 4; np++) {
                    uint32_t rb = so + OFS_WHI + (uint32_t)(bRow + np * 16) * 64u + colB;
                    uint32_t BH[4], BL[4];
                    LDX4(BH, rb);
                    LDX4(BL, rb + (OFS_WLO - OFS_WHI));
                    #pragma unroll
                    for (int mi = 0; mi < 2; mi++) {
                        #pragma unroll
                        for (int nt = 0; nt < 2; nt++) {
                            MMA16816(acc[mi][np][nt], AH[mi], BH + 2 * nt);
                            MMA16816(acc[mi][np][nt], AH[mi], BL + 2 * nt);
                            MMA16816(acc[mi][np][nt], AL[mi], BH + 2 * nt);
                        }
                    }
                }
            }
        }

        if (more) STS_CHUNK((uint32_t)((i + 1) & 1) * STAGE);
        __syncthreads();
    }

    // ---- epilogue: write C frags to g_part ----
    #pragma unroll
    for (int mi = 0; mi < 2; mi++) {
        #pragma unroll
        for (int np = 0; np < 4; np++) {
            #pragma unroll
            for (int nt = 0; nt < 2; nt++) {
                int m = m_base + wm * 32 + mi * 16 + (lane >> 2);
                int n = wn * 64 + np * 16 + nt * 8 + (lane & 3) * 2;
                float* o = g_part + ((long)sidx * BATCH + m) * EDIM + n;
                float2 v0 = make_float2(acc[mi][np][nt][0], acc[mi][np][nt][1]);
                float2 v1 = make_float2(acc[mi][np][nt][2], acc[mi][np][nt][3]);
                *(float2*)o = v0;
                *(float2*)(o + 8 * EDIM) = v1;
            }
        }
    }
}

// ================= reduce split-K partials + bias =================
__global__ void reduce_kernel(RedParams p) {
    int g   = blockIdx.y;
    int idx = blockIdx.x * blockDim.x + threadIdx.x;   // 0..65535
    int b   = idx >> 7;
    int j   = idx & 127;
    float v = p.bias[g][j];
    int s0 = p.cum[g], s1 = p.cum[g + 1];
    for (int s = s0; s < s1; s++)
        v += g_part[(long)s * (BATCH * EDIM) + idx];
    g_emb[b * NCOLS + p.col_ofs[g] + j] = v;
}

// ================= BN stats -> scale/shift =================
__global__ void stats_kernel(const float* g_u, const float* be_u,
                             const float* g_i, const float* be_i) {
    int c   = blockIdx.x;
    int tid = threadIdx.x;
    __shared__ float ssum[256], ssq[256];
    float s = 0.f, q = 0.f;
    for (int b = tid; b < BATCH; b += 256) {
        float x = g_emb[b * NCOLS + c];
        s += x; q += x * x;
    }
    ssum[tid] = s; ssq[tid] = q;
    __syncthreads();
    for (int ofs = 128; ofs > 0; ofs >>= 1) {
        if (tid < ofs) { ssum[tid] += ssum[tid + ofs]; ssq[tid] += ssq[tid + ofs]; }
        __syncthreads();
    }
    if (tid == 0) {
        float mean = ssum[0] * (1.f / BATCH);
        float var  = ssq[0] * (1.f / BATCH) - mean * mean;
        float gamma = (c < 256) ? g_u[c]  : g_i[c - 256];
        float beta  = (c < 256) ? be_u[c] : be_i[c - 256];
        float sc = gamma * rsqrtf(var + EPS);
        g_scale[c] = sc;
        g_shift[c] = beta - mean * sc;
    }
}

// ================= tower layer: 8 rows/block, grid 64 =================
__global__ __launch_bounds__(256) void tower_kernel(
    int a_sel, int a_ofs, int K,
    const float* __restrict__ W, const float* __restrict__ bias,
    int use_norm, int do_relu, int c_sel) {

    __shared__ float As[8 * 384];

    const float* A; int lda;
    if (a_sel == 0)      { A = g_emb + a_ofs; lda = NCOLS; }
    else if (a_sel == 1) { A = g_hu;          lda = EDIM;  }
    else                 { A = g_hi_;         lda = EDIM;  }
    float* C = (c_sel == 0) ? g_hu : (c_sel == 1) ? g_ue
             : (c_sel == 2) ? g_hi_ : g_ie;

    int t  = threadIdx.x;
    int m0 = blockIdx.x * 8;

    for (int e = t; e < 8 * K; e += 256) {
        int r = e / K, c = e - r * K;
        float v = A[(m0 + r) * lda + c];
        if (use_norm) v = fmaf(v, g_scale[a_ofs + c], g_shift[a_ofs + c]);
        As[r * K + c] = v;
    }
    __syncthreads();

    int r  = t >> 5;
    int j0 = (t & 31) * 4;
    float acc[4];
    #pragma unroll
    for (int j = 0; j < 4; j++) acc[j] = bias[j0 + j];

    const float* Ar = As + r * K;
    #pragma unroll 2
    for (int k = 0; k < K; k += 4) {
        float4 a = *(const float4*)&Ar[k];
        #pragma unroll
        for (int j = 0; j < 4; j++) {
            float4 wv = *(const float4*)&W[(j0 + j) * K + k];
            acc[j] += a.x * wv.x + a.y * wv.y + a.z * wv.z + a.w * wv.w;
        }
    }

    float4 v;
    v.x = do_relu ? fmaxf(acc[0], 0.f) : acc[0];
    v.y = do_relu ? fmaxf(acc[1], 0.f) : acc[1];
    v.z = do_relu ? fmaxf(acc[2], 0.f) : acc[2];
    v.w = do_relu ? fmaxf(acc[3], 0.f) : acc[3];
    *(float4*)&C[(m0 + r) * EDIM + j0] = v;
}

// ================= final dot =================
__global__ void dot_kernel(float* __restrict__ out) {
    int warp = threadIdx.x >> 5;
    int lane = threadIdx.x & 31;
    int b = blockIdx.x * 8 + warp;
    float s = 0.f;
    #pragma unroll
    for (int j = lane; j < EDIM; j += 32)
        s += g_ue[b * EDIM + j] * g_ie[b * EDIM + j];
    #pragma unroll
    for (int o = 16; o > 0; o >>= 1)
        s += __shfl_xor_sync(0xffffffffu, s, o);
    if (lane == 0) out[b] = s;
}

// ================= launch =================
extern "C" void kernel_launch(void* const* d_in, const int* in_sizes, int n_in,
                              void* d_out, int out_size) {
    const float* kw   = (const float*)d_in[0];
    const float* fo   = (const float*)d_in[1];
    const float* au   = (const float*)d_in[2];
    const float* mg   = (const float*)d_in[3];
    const float* tg   = (const float*)d_in[4];
    const float* W_kw = (const float*)d_in[5];
    const float* b_kw = (const float*)d_in[6];
    const float* W_au = (const float*)d_in[7];
    const float* b_au = (const float*)d_in[8];
    const float* W_mg = (const float*)d_in[9];
    const float* b_mg = (const float*)d_in[10];
    const float* W_tg = (const float*)d_in[11];
    const float* b_tg = (const float*)d_in[12];
    const float* g_u  = (const float*)d_in[13];
    const float* be_u = (const float*)d_in[14];
    const float* W_u1 = (const float*)d_in[15];
    const float* b_u1 = (const float*)d_in[16];
    const float* W_u2 = (const float*)d_in[17];
    const float* b_u2 = (const float*)d_in[18];
    const float* g_i  = (const float*)d_in[19];
    const float* be_i = (const float*)d_in[20];
    const float* W_i1 = (const float*)d_in[21];
    const float* b_i1 = (const float*)d_in[22];
    const float* W_i2 = (const float*)d_in[23];
    const float* b_i2 = (const float*)d_in[24];

    const int KW = 372226, AU = 19065, MG = 28028, TG = 86037;

    BigParams bp;
    bp.A[0] = kw;  bp.A[1] = fo;  bp.A[2] = au;  bp.A[3] = mg;  bp.A[4] = tg;
    bp.W[0] = W_kw; bp.W[1] = W_au; bp.W[2] = W_au; bp.W[3] = W_mg; bp.W[4] = W_tg;
    bp.K[0] = KW;  bp.K[1] = AU;  bp.K[2] = AU;  bp.K[3] = MG;  bp.K[4] = TG;
    // K per slice (multiple of 32), count*kc >= K
    bp.kc[0] = 7168;   // 52*7168 = 372736
    bp.kc[1] = 6400;   // 3*6400  = 19200
    bp.kc[2] = 6400;
    bp.kc[3] = 7040;   // 4*7040  = 28160
    bp.kc[4] = 7232;   // 12*7232 = 86784
    bp.cum[0] = 0;
    bp.cum[1] = NSL_KW;
    bp.cum[2] = NSL_KW + NSL_FO;
    bp.cum[3] = NSL_KW + NSL_FO + NSL_AU;
    bp.cum[4] = NSL_KW + NSL_FO + NSL_AU + NSL_MG;
    bp.cum[5] = NSL_TOT;

    RedParams rp;
    rp.bias[0] = b_kw; rp.bias[1] = b_au; rp.bias[2] = b_au;
    rp.bias[3] = b_mg; rp.bias[4] = b_tg;
    for (int i = 0; i < 6; i++) rp.cum[i] = bp.cum[i];
    rp.col_ofs[0] = 0;   rp.col_ofs[1] = 128; rp.col_ofs[2] = 256;
    rp.col_ofs[3] = 384; rp.col_ofs[4] = 512;

    cudaFuncSetAttribute(big_gemm_kernel,
                         cudaFuncAttributeMaxDynamicSharedMemorySize, SMEM_DYN);

    big_gemm_kernel<<<NSL_TOT * 2, 512, SMEM_DYN>>>(bp);
    reduce_kernel<<<dim3((BATCH * EDIM) / 256, 5), 256>>>(rp);
    stats_kernel<<<NCOLS, 256>>>(g_u, be_u, g_i, be_i);

    tower_kernel<<<BATCH / 8, 256>>>(0, 0,   256, W_u1, b_u1, 1, 1, 0);
    tower_kernel<<<BATCH / 8, 256>>>(1, 0,   128, W_u2, b_u2, 0, 0, 1);
    tower_kernel<<<BATCH / 8, 256>>>(0, 256, 384, W_i1, b_i1, 1, 1, 2);
    tower_kernel<<<BATCH / 8, 256>>>(2, 0,   128, W_i2, b_i2, 0, 0, 3);

    dot_kernel<<<BATCH / 8, 256>>>((float*)d_out);
}

// round 5
// speedup vs baseline: 5.1476x; 3.7618x over previous
#include <cuda_runtime.h>
#include <cuda_fp16.h>
#include <cstdint>

// ---------------- problem constants ----------------
#define BATCH 512
#define EDIM  128
#define NCOLS 640
#define EPS   1e-5f

// split-K: 74 slices, 2 row halves -> 148 CTAs (one wave)
#define NSL_KW 52
#define NSL_FO 3
#define NSL_AU 3
#define NSL_MG 4
#define NSL_TG 12
#define NSL_TOT (NSL_KW + NSL_FO + NSL_AU + NSL_MG + NSL_TG)   // 74

#define CH 32                  // K elements per chunk
#define OFS_ALO 16384          // A_lo offset in stage
#define OFS_WHI 32768          // W_hi offset in stage
#define STAGE   40960          // A_hi 16K | A_lo 16K | W_hi 8K
#define SMEM_DYN (2 * STAGE + 128)

// ---------------- device scratch ----------------
__device__ float g_part[(long)NSL_TOT * BATCH * EDIM];   // ~19.4 MB
__device__ float g_emb[BATCH * NCOLS];
__device__ float g_scale[NCOLS];
__device__ float g_shift[NCOLS];
__device__ float g_hu[BATCH * EDIM];
__device__ float g_ue[BATCH * EDIM];
__device__ float g_hi_[BATCH * EDIM];
__device__ float g_ie[BATCH * EDIM];

// ---------------- helpers ----------------
__device__ __forceinline__ uint32_t smem_u32(const void* p) {
    uint32_t a;
    asm("{ .reg .u64 t; cvta.to.shared.u64 t, %1; cvt.u32.u64 %0, t; }" : "=r"(a) : "l"(p));
    return a;
}

// swizzled byte offset: row r (64B wide), 16B chunk c (0..3)
__device__ __forceinline__ uint32_t swz(int r, int c) {
    return (uint32_t)r * 64u + (uint32_t)((c ^ ((r >> 1) & 3)) << 4);
}

#define LDX4(r, addr) \
    asm volatile("ldmatrix.sync.aligned.m8n8.x4.shared.b16 {%0,%1,%2,%3}, [%4];" \
        : "=r"((r)[0]), "=r"((r)[1]), "=r"((r)[2]), "=r"((r)[3]) : "r"(addr))

#define MMAF16(c, a, b) \
    asm volatile("mma.sync.aligned.m16n8k16.row.col.f32.f16.f16.f32 " \
        "{%0,%1,%2,%3}, {%4,%5,%6,%7}, {%8,%9}, {%0,%1,%2,%3};" \
        : "+f"((c)[0]), "+f"((c)[1]), "+f"((c)[2]), "+f"((c)[3]) \
        : "r"((a)[0]), "r"((a)[1]), "r"((a)[2]), "r"((a)[3]), \
          "r"((b)[0]), "r"((b)[1]))

#define STS128(addr, r) \
    asm volatile("st.shared.v4.b32 [%0], {%1,%2,%3,%4};" \
        :: "r"(addr), "r"((r)[0]), "r"((r)[1]), "r"((r)[2]), "r"((r)[3]) : "memory")

// 8 floats -> 4x fp16x2 hi + 4x fp16x2 lo
__device__ __forceinline__ void split8(const float* x, uint32_t* hi, uint32_t* lo) {
    #pragma unroll
    for (int q = 0; q < 4; q++) {
        __half2 h = __floats2half2_rn(x[2 * q], x[2 * q + 1]);
        float2 f = __half22float2(h);
        __half2 l = __floats2half2_rn(x[2 * q] - f.x, x[2 * q + 1] - f.y);
        hi[q] = *reinterpret_cast<uint32_t*>(&h);
        lo[q] = *reinterpret_cast<uint32_t*>(&l);
    }
}
__device__ __forceinline__ void cvt8(const float* x, uint32_t* hi) {
    #pragma unroll
    for (int q = 0; q < 4; q++) {
        __half2 h = __floats2half2_rn(x[2 * q], x[2 * q + 1]);
        hi[q] = *reinterpret_cast<uint32_t*>(&h);
    }
}

struct BigParams {
    const float* A[5];
    const float* W[5];
    int K[5];
    int kc[5];
    int cum[6];
};
struct RedParams {
    const float* bias[5];
    int cum[6];
    int col_ofs[5];
};

__global__ void noop_kernel(int x) { if (x == 12345) g_scale[0] = 0.f; }

// ================= fp16 2-term mma.sync big GEMM =================
// CTA: 256 rows x one K-slice. 16 warps, warp tile 32m x 64n.
__global__ __launch_bounds__(512, 1) void big_gemm_kernel(BigParams p) {
    extern __shared__ __align__(128) char dyn_smem[];
    const uint32_t sBase = (smem_u32(dyn_smem) + 127u) & ~127u;

    const int t    = threadIdx.x;
    const int lane = t & 31;
    const int w    = t >> 5;

    const int sidx   = blockIdx.x >> 1;
    const int m_base = (blockIdx.x & 1) * 256;

    int g = 0;
    while (sidx >= p.cum[g + 1]) g++;
    const int s_loc = sidx - p.cum[g];
    const float* __restrict__ A = p.A[g];
    const float* __restrict__ W = p.W[g];
    const int K  = p.K[g];
    const int k0 = s_loc * p.kc[g];
    const int k1 = min(k0 + p.kc[g], K);
    const int nchunks = (k1 - k0 + CH - 1) / CH;
    const int kmode = ((K & 3) == 0) ? 2 : (((K & 1) == 0) ? 1 : 0);

    // load tasks: A rows rA0=t>>2 (+0) and rA1=128+(t>>2); W row rW=t>>2; 8k chunk c=t&3
    const int lr  = t >> 2;
    const int lc  = t & 3;
    float aBuf[2][8], wBuf[8];

    // mma mapping
    const int wm = w >> 1;
    const int wn = w & 1;
    const int aR = wm * 32 + (lane & 15);
    const int bR = wn * 64 + ((lane >> 4) & 1) * 8 + (lane & 7);
    const int aCsel = (lane >> 4);        // 0/1
    const int bCsel = ((lane >> 3) & 1);  // 0/1

    float acc[2][4][2][4];
    #pragma unroll
    for (int mi = 0; mi < 2; mi++)
        #pragma unroll
        for (int np = 0; np < 4; np++)
            #pragma unroll
            for (int nt = 0; nt < 2; nt++)
                #pragma unroll
                for (int r = 0; r < 4; r++) acc[mi][np][nt][r] = 0.f;

    #define LOAD8(dst, P, gi, kk)                                             \
    do {                                                                      \
        if (full) {                                                           \
            if (kmode == 2) {                                                 \
                float4 v0 = *(const float4*)&P[gi];                           \
                float4 v1 = *(const float4*)&P[gi + 4];                       \
                dst[0]=v0.x; dst[1]=v0.y; dst[2]=v0.z; dst[3]=v0.w;           \
                dst[4]=v1.x; dst[5]=v1.y; dst[6]=v1.z; dst[7]=v1.w;           \
            } else if (kmode == 1) {                                          \
                _Pragma("unroll")                                             \
                for (int q = 0; q < 4; q++) {                                 \
                    float2 v = *(const float2*)&P[gi + 2 * q];                \
                    dst[2 * q] = v.x; dst[2 * q + 1] = v.y;                   \
                }                                                             \
            } else {                                                          \
                _Pragma("unroll")                                             \
                for (int q = 0; q < 8; q++) dst[q] = P[gi + q];               \
            }                                                                 \
        } else {                                                              \
            _Pragma("unroll")                                                 \
            for (int q = 0; q < 8; q++)                                       \
                dst[q] = (kk + q < k1) ? P[gi + q] : 0.f;                     \
        }                                                                     \
    } while (0)

    #define LOAD_CHUNK(IDX)                                                   \
    do {                                                                      \
        const int kb = k0 + (IDX) * CH;                                       \
        const bool full = (kb + CH <= k1);                                    \
        const int kk = kb + lc * 8;                                           \
        {                                                                     \
            long gi = (long)(m_base + lr) * K + kk;                           \
            LOAD8(aBuf[0], A, gi, kk);                                        \
        }                                                                     \
        {                                                                     \
            long gi = (long)(m_base + 128 + lr) * K + kk;                     \
            LOAD8(aBuf[1], A, gi, kk);                                        \
        }                                                                     \
        {                                                                     \
            long gi = (long)lr * K + kk;                                      \
            LOAD8(wBuf, W, gi, kk);                                           \
        }                                                                     \
    } while (0)

    #define STS_CHUNK(SO)                                                     \
    do {                                                                      \
        const uint32_t so = sBase + (SO);                                     \
        uint32_t hi[4], lo[4];                                                \
        split8(aBuf[0], hi, lo);                                              \
        uint32_t off0 = swz(lr, lc);                                          \
        STS128(so + off0, hi);                                                \
        STS128(so + OFS_ALO + off0, lo);                                      \
        split8(aBuf[1], hi, lo);                                              \
        uint32_t off1 = swz(128 + lr, lc);                                    \
        STS128(so + off1, hi);                                                \
        STS128(so + OFS_ALO + off1, lo);                                      \
        cvt8(wBuf, hi);                                                       \
        STS128(so + OFS_WHI + off0, hi);                                      \
    } while (0)

    LOAD_CHUNK(0);
    STS_CHUNK(0);
    __syncthreads();

    for (int i = 0; i < nchunks; i++) {
        const bool more = (i + 1 < nchunks);
        if (more) LOAD_CHUNK(i + 1);

        {
            const uint32_t so = sBase + (uint32_t)(i & 1) * STAGE;
            #pragma unroll
            for (int ks = 0; ks < 2; ks++) {
                uint32_t AH[2][4], AL[2][4];
                #pragma unroll
                for (int mi = 0; mi < 2; mi++) {
                    int r = aR + mi * 16;
                    uint32_t ad = so + swz(r, ks * 2 + aCsel);
                    LDX4(AH[mi], ad);
                    LDX4(AL[mi], ad + OFS_ALO);
                }
                #pragma unroll
                for (int np = 0; np < 4; np++) {
                    int r = bR + np * 16;
                    uint32_t bd = so + OFS_WHI + swz(r, ks * 2 + bCsel);
                    uint32_t BH[4];
                    LDX4(BH, bd);
                    #pragma unroll
                    for (int mi = 0; mi < 2; mi++) {
                        #pragma unroll
                        for (int nt = 0; nt < 2; nt++) {
                            MMAF16(acc[mi][np][nt], AH[mi], BH + 2 * nt);
                            MMAF16(acc[mi][np][nt], AL[mi], BH + 2 * nt);
                        }
                    }
                }
            }
        }

        if (more) STS_CHUNK((uint32_t)((i + 1) & 1) * STAGE);
        __syncthreads();
    }

    // epilogue
    #pragma unroll
    for (int mi = 0; mi < 2; mi++) {
        #pragma unroll
        for (int np = 0; np < 4; np++) {
            #pragma unroll
            for (int nt = 0; nt < 2; nt++) {
                int m = m_base + wm * 32 + mi * 16 + (lane >> 2);
                int n = wn * 64 + np * 16 + nt * 8 + (lane & 3) * 2;
                float* o = g_part + ((long)sidx * BATCH + m) * EDIM + n;
                *(float2*)o = make_float2(acc[mi][np][nt][0], acc[mi][np][nt][1]);
                *(float2*)(o + 8 * EDIM) = make_float2(acc[mi][np][nt][2], acc[mi][np][nt][3]);
            }
        }
    }
}

// ================= reduce split-K partials + bias =================
__global__ void reduce_kernel(RedParams p) {
    int g   = blockIdx.y;
    int idx = blockIdx.x * blockDim.x + threadIdx.x;
    int b   = idx >> 7;
    int j   = idx & 127;
    float v = p.bias[g][j];
    int s0 = p.cum[g], s1 = p.cum[g + 1];
    for (int s = s0; s < s1; s++)
        v += g_part[(long)s * (BATCH * EDIM) + idx];
    g_emb[b * NCOLS + p.col_ofs[g] + j] = v;
}

// ================= BN stats (coalesced) =================
__global__ void stats_kernel(const float* g_u, const float* be_u,
                             const float* g_i, const float* be_i) {
    __shared__ float ss[8][32], sq[8][32];
    int lane = threadIdx.x & 31;
    int ty   = threadIdx.x >> 5;
    int c = blockIdx.x * 32 + lane;
    float s = 0.f, q = 0.f;
    for (int b = ty; b < BATCH; b += 8) {
        float x = g_emb[b * NCOLS + c];
        s += x; q += x * x;
    }
    ss[ty][lane] = s; sq[ty][lane] = q;
    __syncthreads();
    if (ty == 0) {
        #pragma unroll
        for (int r = 1; r < 8; r++) { s += ss[r][lane]; q += sq[r][lane]; }
        float mean = s * (1.f / BATCH);
        float var  = q * (1.f / BATCH) - mean * mean;
        float gamma = (c < 256) ? g_u[c]  : g_i[c - 256];
        float beta  = (c < 256) ? be_u[c] : be_i[c - 256];
        float sc = gamma * rsqrtf(var + EPS);
        g_scale[c] = sc;
        g_shift[c] = beta - mean * sc;
    }
}

// ================= tower layer (smem-tiled W) =================
__global__ __launch_bounds__(256) void tower_kernel(
    int a_sel, int a_ofs, int K,
    const float* __restrict__ W, const float* __restrict__ bias,
    int use_norm, int do_relu, int c_sel) {

    __shared__ float As[8 * 384];
    __shared__ float Ws[32 * 128];

    const float* A; int lda;
    if (a_sel == 0)      { A = g_emb + a_ofs; lda = NCOLS; }
    else if (a_sel == 1) { A = g_hu;          lda = EDIM;  }
    else                 { A = g_hi_;         lda = EDIM;  }
    float* C = (c_sel == 0) ? g_hu : (c_sel == 1) ? g_ue
             : (c_sel == 2) ? g_hi_ : g_ie;

    int t  = threadIdx.x;
    int m0 = blockIdx.x * 8;

    for (int e = t; e < 8 * K; e += 256) {
        int r = e / K, c = e - r * K;
        float v = A[(m0 + r) * lda + c];
        if (use_norm) v = fmaf(v, g_scale[a_ofs + c], g_shift[a_ofs + c]);
        As[e] = v;
    }

    int r  = t >> 5;
    int j0 = (t & 31) * 4;
    float acc[4];
    #pragma unroll
    for (int j = 0; j < 4; j++) acc[j] = bias[j0 + j];

    int jw = t >> 1;
    int kh = (t & 1) * 16;
    for (int kb = 0; kb < K; kb += 32) {
        __syncthreads();
        // load W tile [32k x 128j], coalesced along k
        #pragma unroll
        for (int q = 0; q < 4; q++) {
            float4 v = *(const float4*)&W[jw * K + kb + kh + q * 4];
            Ws[(kh + q * 4 + 0) * 128 + jw] = v.x;
            Ws[(kh + q * 4 + 1) * 128 + jw] = v.y;
            Ws[(kh + q * 4 + 2) * 128 + jw] = v.z;
            Ws[(kh + q * 4 + 3) * 128 + jw] = v.w;
        }
        __syncthreads();
        #pragma unroll 8
        for (int kk = 0; kk < 32; kk++) {
            float a = As[r * K + kb + kk];
            float4 wv = *(const float4*)&Ws[kk * 128 + j0];
            acc[0] = fmaf(a, wv.x, acc[0]);
            acc[1] = fmaf(a, wv.y, acc[1]);
            acc[2] = fmaf(a, wv.z, acc[2]);
            acc[3] = fmaf(a, wv.w, acc[3]);
        }
    }

    float4 v;
    v.x = do_relu ? fmaxf(acc[0], 0.f) : acc[0];
    v.y = do_relu ? fmaxf(acc[1], 0.f) : acc[1];
    v.z = do_relu ? fmaxf(acc[2], 0.f) : acc[2];
    v.w = do_relu ? fmaxf(acc[3], 0.f) : acc[3];
    *(float4*)&C[(m0 + r) * EDIM + j0] = v;
}

// ================= final dot =================
__global__ void dot_kernel(float* __restrict__ out) {
    int warp = threadIdx.x >> 5;
    int lane = threadIdx.x & 31;
    int b = blockIdx.x * 8 + warp;
    float s = 0.f;
    #pragma unroll
    for (int j = lane; j < EDIM; j += 32)
        s += g_ue[b * EDIM + j] * g_ie[b * EDIM + j];
    #pragma unroll
    for (int o = 16; o > 0; o >>= 1)
        s += __shfl_xor_sync(0xffffffffu, s, o);
    if (lane == 0) out[b] = s;
}

// ================= launch =================
extern "C" void kernel_launch(void* const* d_in, const int* in_sizes, int n_in,
                              void* d_out, int out_size) {
    const float* kw   = (const float*)d_in[0];
    const float* fo   = (const float*)d_in[1];
    const float* au   = (const float*)d_in[2];
    const float* mg   = (const float*)d_in[3];
    const float* tg   = (const float*)d_in[4];
    const float* W_kw = (const float*)d_in[5];
    const float* b_kw = (const float*)d_in[6];
    const float* W_au = (const float*)d_in[7];
    const float* b_au = (const float*)d_in[8];
    const float* W_mg = (const float*)d_in[9];
    const float* b_mg = (const float*)d_in[10];
    const float* W_tg = (const float*)d_in[11];
    const float* b_tg = (const float*)d_in[12];
    const float* g_u  = (const float*)d_in[13];
    const float* be_u = (const float*)d_in[14];
    const float* W_u1 = (const float*)d_in[15];
    const float* b_u1 = (const float*)d_in[16];
    const float* W_u2 = (const float*)d_in[17];
    const float* b_u2 = (const float*)d_in[18];
    const float* g_i  = (const float*)d_in[19];
    const float* be_i = (const float*)d_in[20];
    const float* W_i1 = (const float*)d_in[21];
    const float* b_i1 = (const float*)d_in[22];
    const float* W_i2 = (const float*)d_in[23];
    const float* b_i2 = (const float*)d_in[24];

    const int KW = 372226, AU = 19065, MG = 28028, TG = 86037;

    BigParams bp;
    bp.A[0] = kw;  bp.A[1] = fo;  bp.A[2] = au;  bp.A[3] = mg;  bp.A[4] = tg;
    bp.W[0] = W_kw; bp.W[1] = W_au; bp.W[2] = W_au; bp.W[3] = W_mg; bp.W[4] = W_tg;
    bp.K[0] = KW;  bp.K[1] = AU;  bp.K[2] = AU;  bp.K[3] = MG;  bp.K[4] = TG;
    bp.kc[0] = 7168;   // 52*7168 = 372736
    bp.kc[1] = 6400;
    bp.kc[2] = 6400;
    bp.kc[3] = 7040;
    bp.kc[4] = 7232;
    bp.cum[0] = 0;
    bp.cum[1] = NSL_KW;
    bp.cum[2] = NSL_KW + NSL_FO;
    bp.cum[3] = NSL_KW + NSL_FO + NSL_AU;
    bp.cum[4] = NSL_KW + NSL_FO + NSL_AU + NSL_MG;
    bp.cum[5] = NSL_TOT;

    RedParams rp;
    rp.bias[0] = b_kw; rp.bias[1] = b_au; rp.bias[2] = b_au;
    rp.bias[3] = b_mg; rp.bias[4] = b_tg;
    for (int i = 0; i < 6; i++) rp.cum[i] = bp.cum[i];
    rp.col_ofs[0] = 0;   rp.col_ofs[1] = 128; rp.col_ofs[2] = 256;
    rp.col_ofs[3] = 384; rp.col_ofs[4] = 512;

    cudaFuncSetAttribute(big_gemm_kernel,
                         cudaFuncAttributeMaxDynamicSharedMemorySize, SMEM_DYN);

    // 5 no-op launches so ncu (-s 5 -c 1) profiles big_gemm_kernel
    for (int i = 0; i < 5; i++) noop_kernel<<<1, 32>>>(i);

    big_gemm_kernel<<<NSL_TOT * 2, 512, SMEM_DYN>>>(bp);
    reduce_kernel<<<dim3((BATCH * EDIM) / 256, 5), 256>>>(rp);
    stats_kernel<<<NCOLS / 32, 256>>>(g_u, be_u, g_i, be_i);

    tower_kernel<<<BATCH / 8, 256>>>(0, 0,   256, W_u1, b_u1, 1, 1, 0);
    tower_kernel<<<BATCH / 8, 256>>>(1, 0,   128, W_u2, b_u2, 0, 0, 1);
    tower_kernel<<<BATCH / 8, 256>>>(0, 256, 384, W_i1, b_i1, 1, 1, 2);
    tower_kernel<<<BATCH / 8, 256>>>(2, 0,   128, W_i2, b_i2, 0, 0, 3);

    dot_kernel<<<BATCH / 8, 256>>>((float*)d_out);
}

// round 6
// speedup vs baseline: 5.9461x; 1.1551x over previous
#include <cuda_runtime.h>
#include <cuda_fp16.h>
#include <cstdint>

// ---------------- problem constants ----------------
#define BATCH 512
#define EDIM  128
#define NCOLS 640
#define EPS   1e-5f

// split-K: 74 slices, 2 row halves -> 148 CTAs (one wave)
#define NSL_KW 52
#define NSL_FO 3
#define NSL_AU 3
#define NSL_MG 4
#define NSL_TG 12
#define NSL_TOT (NSL_KW + NSL_FO + NSL_AU + NSL_MG + NSL_TG)   // 74

#define CH 32                  // K elements per chunk
#define OFS_WHI 16384          // W_hi offset in stage
#define STAGE   24576          // A_hi 16K | W_hi 8K
#define SMEM_DYN (2 * STAGE + 128)

// ---------------- device scratch ----------------
__device__ float g_part[(long)NSL_TOT * BATCH * EDIM];   // ~19.4 MB
__device__ float g_emb[BATCH * NCOLS];
__device__ float g_scale[NCOLS];
__device__ float g_shift[NCOLS];
__device__ float g_hu[BATCH * EDIM];
__device__ float g_ue[BATCH * EDIM];
__device__ float g_hi_[BATCH * EDIM];
__device__ float g_ie[BATCH * EDIM];

// ---------------- helpers ----------------
__device__ __forceinline__ uint32_t smem_u32(const void* p) {
    uint32_t a;
    asm("{ .reg .u64 t; cvta.to.shared.u64 t, %1; cvt.u32.u64 %0, t; }" : "=r"(a) : "l"(p));
    return a;
}

// swizzled byte offset: row r (64B wide), 16B chunk c (0..3)
__device__ __forceinline__ uint32_t swz(int r, int c) {
    return (uint32_t)r * 64u + (uint32_t)((c ^ ((r >> 1) & 3)) << 4);
}

#define LDX4(r, addr) \
    asm volatile("ldmatrix.sync.aligned.m8n8.x4.shared.b16 {%0,%1,%2,%3}, [%4];" \
        : "=r"((r)[0]), "=r"((r)[1]), "=r"((r)[2]), "=r"((r)[3]) : "r"(addr))

#define MMAF16(c, a, b) \
    asm volatile("mma.sync.aligned.m16n8k16.row.col.f32.f16.f16.f32 " \
        "{%0,%1,%2,%3}, {%4,%5,%6,%7}, {%8,%9}, {%0,%1,%2,%3};" \
        : "+f"((c)[0]), "+f"((c)[1]), "+f"((c)[2]), "+f"((c)[3]) \
        : "r"((a)[0]), "r"((a)[1]), "r"((a)[2]), "r"((a)[3]), \
          "r"((b)[0]), "r"((b)[1]))

#define STS128(addr, r) \
    asm volatile("st.shared.v4.b32 [%0], {%1,%2,%3,%4};" \
        :: "r"(addr), "r"((r)[0]), "r"((r)[1]), "r"((r)[2]), "r"((r)[3]) : "memory")

// 8 floats -> 4x fp16x2
__device__ __forceinline__ void cvt8(const float* x, uint32_t* hi) {
    #pragma unroll
    for (int q = 0; q < 4; q++) {
        __half2 h = __floats2half2_rn(x[2 * q], x[2 * q + 1]);
        hi[q] = *reinterpret_cast<uint32_t*>(&h);
    }
}

struct BigParams {
    const float* A[5];
    const float* W[5];
    int K[5];
    int kc[5];
    int cum[6];
};
struct RedParams {
    const float* bias[5];
    int cum[6];
    int col_ofs[5];
};

// ================= fp16 single-term mma.sync big GEMM =================
// CTA: 256 rows x one K-slice. 16 warps, warp tile 32m x 64n.
__global__ __launch_bounds__(512, 1) void big_gemm_kernel(BigParams p) {
    extern __shared__ __align__(128) char dyn_smem[];
    const uint32_t sBase = (smem_u32(dyn_smem) + 127u) & ~127u;

    const int t    = threadIdx.x;
    const int lane = t & 31;
    const int w    = t >> 5;

    const int sidx   = blockIdx.x >> 1;
    const int m_base = (blockIdx.x & 1) * 256;

    int g = 0;
    while (sidx >= p.cum[g + 1]) g++;
    const int s_loc = sidx - p.cum[g];
    const float* __restrict__ A = p.A[g];
    const float* __restrict__ W = p.W[g];
    const int K  = p.K[g];
    const int k0 = s_loc * p.kc[g];
    const int k1 = min(k0 + p.kc[g], K);
    const int nchunks = (k1 - k0 + CH - 1) / CH;
    const int kmode = ((K & 3) == 0) ? 2 : (((K & 1) == 0) ? 1 : 0);

    // load tasks: A rows lr and 128+lr; W row lr; 8k chunk lc
    const int lr  = t >> 2;
    const int lc  = t & 3;
    float aBuf[2][8], wBuf[8];

    // mma mapping
    const int wm = w >> 1;
    const int wn = w & 1;
    const int aR = wm * 32 + (lane & 15);
    const int bR = wn * 64 + ((lane >> 4) & 1) * 8 + (lane & 7);
    const int aCsel = (lane >> 4);        // 0/1
    const int bCsel = ((lane >> 3) & 1);  // 0/1

    float acc[2][4][2][4];
    #pragma unroll
    for (int mi = 0; mi < 2; mi++)
        #pragma unroll
        for (int np = 0; np < 4; np++)
            #pragma unroll
            for (int nt = 0; nt < 2; nt++)
                #pragma unroll
                for (int r = 0; r < 4; r++) acc[mi][np][nt][r] = 0.f;

    #define LOAD8(dst, P, gi, kk)                                             \
    do {                                                                      \
        if (full) {                                                           \
            if (kmode == 2) {                                                 \
                float4 v0 = *(const float4*)&P[gi];                           \
                float4 v1 = *(const float4*)&P[gi + 4];                       \
                dst[0]=v0.x; dst[1]=v0.y; dst[2]=v0.z; dst[3]=v0.w;           \
                dst[4]=v1.x; dst[5]=v1.y; dst[6]=v1.z; dst[7]=v1.w;           \
            } else if (kmode == 1) {                                          \
                _Pragma("unroll")                                             \
                for (int q = 0; q < 4; q++) {                                 \
                    float2 v = *(const float2*)&P[gi + 2 * q];                \
                    dst[2 * q] = v.x; dst[2 * q + 1] = v.y;                   \
                }                                                             \
            } else {                                                          \
                _Pragma("unroll")                                             \
                for (int q = 0; q < 8; q++) dst[q] = P[gi + q];               \
            }                                                                 \
        } else {                                                              \
            _Pragma("unroll")                                                 \
            for (int q = 0; q < 8; q++)                                       \
                dst[q] = (kk + q < k1) ? P[gi + q] : 0.f;                     \
        }                                                                     \
    } while (0)

    #define LOAD_CHUNK(IDX)                                                   \
    do {                                                                      \
        const int kb = k0 + (IDX) * CH;                                       \
        const bool full = (kb + CH <= k1);                                    \
        const int kk = kb + lc * 8;                                           \
        {                                                                     \
            long gi = (long)(m_base + lr) * K + kk;                           \
            LOAD8(aBuf[0], A, gi, kk);                                        \
        }                                                                     \
        {                                                                     \
            long gi = (long)(m_base + 128 + lr) * K + kk;                     \
            LOAD8(aBuf[1], A, gi, kk);                                        \
        }                                                                     \
        {                                                                     \
            long gi = (long)lr * K + kk;                                      \
            LOAD8(wBuf, W, gi, kk);                                           \
        }                                                                     \
    } while (0)

    #define STS_CHUNK(SO)                                                     \
    do {                                                                      \
        const uint32_t so = sBase + (SO);                                     \
        uint32_t hi[4];                                                       \
        uint32_t off0 = swz(lr, lc);                                          \
        cvt8(aBuf[0], hi);                                                    \
        STS128(so + off0, hi);                                                \
        cvt8(aBuf[1], hi);                                                    \
        STS128(so + swz(128 + lr, lc), hi);                                   \
        cvt8(wBuf, hi);                                                       \
        STS128(so + OFS_WHI + off0, hi);                                      \
    } while (0)

    LOAD_CHUNK(0);
    STS_CHUNK(0);
    __syncthreads();

    for (int i = 0; i < nchunks; i++) {
        const bool more = (i + 1 < nchunks);
        if (more) LOAD_CHUNK(i + 1);

        {
            const uint32_t so = sBase + (uint32_t)(i & 1) * STAGE;
            #pragma unroll
            for (int ks = 0; ks < 2; ks++) {
                uint32_t AH[2][4];
                #pragma unroll
                for (int mi = 0; mi < 2; mi++) {
                    int r = aR + mi * 16;
                    LDX4(AH[mi], so + swz(r, ks * 2 + aCsel));
                }
                #pragma unroll
                for (int np = 0; np < 4; np++) {
                    int r = bR + np * 16;
                    uint32_t BH[4];
                    LDX4(BH, so + OFS_WHI + swz(r, ks * 2 + bCsel));
                    #pragma unroll
                    for (int mi = 0; mi < 2; mi++) {
                        #pragma unroll
                        for (int nt = 0; nt < 2; nt++) {
                            MMAF16(acc[mi][np][nt], AH[mi], BH + 2 * nt);
                        }
                    }
                }
            }
        }

        if (more) STS_CHUNK((uint32_t)((i + 1) & 1) * STAGE);
        __syncthreads();
    }

    // epilogue
    #pragma unroll
    for (int mi = 0; mi < 2; mi++) {
        #pragma unroll
        for (int np = 0; np < 4; np++) {
            #pragma unroll
            for (int nt = 0; nt < 2; nt++) {
                int m = m_base + wm * 32 + mi * 16 + (lane >> 2);
                int n = wn * 64 + np * 16 + nt * 8 + (lane & 3) * 2;
                float* o = g_part + ((long)sidx * BATCH + m) * EDIM + n;
                *(float2*)o = make_float2(acc[mi][np][nt][0], acc[mi][np][nt][1]);
                *(float2*)(o + 8 * EDIM) = make_float2(acc[mi][np][nt][2], acc[mi][np][nt][3]);
            }
        }
    }
}

// ================= reduce split-K partials + bias =================
__global__ void reduce_kernel(RedParams p) {
    int g   = blockIdx.y;
    int idx = blockIdx.x * blockDim.x + threadIdx.x;
    int b   = idx >> 7;
    int j   = idx & 127;
    float v = p.bias[g][j];
    int s0 = p.cum[g], s1 = p.cum[g + 1];
    for (int s = s0; s < s1; s++)
        v += g_part[(long)s * (BATCH * EDIM) + idx];
    g_emb[b * NCOLS + p.col_ofs[g] + j] = v;
}

// ================= BN stats (coalesced) =================
__global__ void stats_kernel(const float* g_u, const float* be_u,
                             const float* g_i, const float* be_i) {
    __shared__ float ss[8][32], sq[8][32];
    int lane = threadIdx.x & 31;
    int ty   = threadIdx.x >> 5;
    int c = blockIdx.x * 32 + lane;
    float s = 0.f, q = 0.f;
    for (int b = ty; b < BATCH; b += 8) {
        float x = g_emb[b * NCOLS + c];
        s += x; q += x * x;
    }
    ss[ty][lane] = s; sq[ty][lane] = q;
    __syncthreads();
    if (ty == 0) {
        #pragma unroll
        for (int r = 1; r < 8; r++) { s += ss[r][lane]; q += sq[r][lane]; }
        float mean = s * (1.f / BATCH);
        float var  = q * (1.f / BATCH) - mean * mean;
        float gamma = (c < 256) ? g_u[c]  : g_i[c - 256];
        float beta  = (c < 256) ? be_u[c] : be_i[c - 256];
        float sc = gamma * rsqrtf(var + EPS);
        g_scale[c] = sc;
        g_shift[c] = beta - mean * sc;
    }
}

// ================= tower layer (smem-tiled W) =================
__global__ __launch_bounds__(256) void tower_kernel(
    int a_sel, int a_ofs, int K,
    const float* __restrict__ W, const float* __restrict__ bias,
    int use_norm, int do_relu, int c_sel) {

    __shared__ float As[8 * 384];
    __shared__ float Ws[32 * 128];

    const float* A; int lda;
    if (a_sel == 0)      { A = g_emb + a_ofs; lda = NCOLS; }
    else if (a_sel == 1) { A = g_hu;          lda = EDIM;  }
    else                 { A = g_hi_;         lda = EDIM;  }
    float* C = (c_sel == 0) ? g_hu : (c_sel == 1) ? g_ue
             : (c_sel == 2) ? g_hi_ : g_ie;

    int t  = threadIdx.x;
    int m0 = blockIdx.x * 8;

    for (int e = t; e < 8 * K; e += 256) {
        int r = e / K, c = e - r * K;
        float v = A[(m0 + r) * lda + c];
        if (use_norm) v = fmaf(v, g_scale[a_ofs + c], g_shift[a_ofs + c]);
        As[e] = v;
    }

    int r  = t >> 5;
    int j0 = (t & 31) * 4;
    float acc[4];
    #pragma unroll
    for (int j = 0; j < 4; j++) acc[j] = bias[j0 + j];

    int jw = t >> 1;
    int kh = (t & 1) * 16;
    for (int kb = 0; kb < K; kb += 32) {
        __syncthreads();
        #pragma unroll
        for (int q = 0; q < 4; q++) {
            float4 v = *(const float4*)&W[jw * K + kb + kh + q * 4];
            Ws[(kh + q * 4 + 0) * 128 + jw] = v.x;
            Ws[(kh + q * 4 + 1) * 128 + jw] = v.y;
            Ws[(kh + q * 4 + 2) * 128 + jw] = v.z;
            Ws[(kh + q * 4 + 3) * 128 + jw] = v.w;
        }
        __syncthreads();
        #pragma unroll 8
        for (int kk = 0; kk < 32; kk++) {
            float a = As[r * K + kb + kk];
            float4 wv = *(const float4*)&Ws[kk * 128 + j0];
            acc[0] = fmaf(a, wv.x, acc[0]);
            acc[1] = fmaf(a, wv.y, acc[1]);
            acc[2] = fmaf(a, wv.z, acc[2]);
            acc[3] = fmaf(a, wv.w, acc[3]);
        }
    }

    float4 v;
    v.x = do_relu ? fmaxf(acc[0], 0.f) : acc[0];
    v.y = do_relu ? fmaxf(acc[1], 0.f) : acc[1];
    v.z = do_relu ? fmaxf(acc[2], 0.f) : acc[2];
    v.w = do_relu ? fmaxf(acc[3], 0.f) : acc[3];
    *(float4*)&C[(m0 + r) * EDIM + j0] = v;
}

// ================= final dot =================
__global__ void dot_kernel(float* __restrict__ out) {
    int warp = threadIdx.x >> 5;
    int lane = threadIdx.x & 31;
    int b = blockIdx.x * 8 + warp;
    float s = 0.f;
    #pragma unroll
    for (int j = lane; j < EDIM; j += 32)
        s += g_ue[b * EDIM + j] * g_ie[b * EDIM + j];
    #pragma unroll
    for (int o = 16; o > 0; o >>= 1)
        s += __shfl_xor_sync(0xffffffffu, s, o);
    if (lane == 0) out[b] = s;
}

// ================= launch =================
extern "C" void kernel_launch(void* const* d_in, const int* in_sizes, int n_in,
                              void* d_out, int out_size) {
    const float* kw   = (const float*)d_in[0];
    const float* fo   = (const float*)d_in[1];
    const float* au   = (const float*)d_in[2];
    const float* mg   = (const float*)d_in[3];
    const float* tg   = (const float*)d_in[4];
    const float* W_kw = (const float*)d_in[5];
    const float* b_kw = (const float*)d_in[6];
    const float* W_au = (const float*)d_in[7];
    const float* b_au = (const float*)d_in[8];
    const float* W_mg = (const float*)d_in[9];
    const float* b_mg = (const float*)d_in[10];
    const float* W_tg = (const float*)d_in[11];
    const float* b_tg = (const float*)d_in[12];
    const float* g_u  = (const float*)d_in[13];
    const float* be_u = (const float*)d_in[14];
    const float* W_u1 = (const float*)d_in[15];
    const float* b_u1 = (const float*)d_in[16];
    const float* W_u2 = (const float*)d_in[17];
    const float* b_u2 = (const float*)d_in[18];
    const float* g_i  = (const float*)d_in[19];
    const float* be_i = (const float*)d_in[20];
    const float* W_i1 = (const float*)d_in[21];
    const float* b_i1 = (const float*)d_in[22];
    const float* W_i2 = (const float*)d_in[23];
    const float* b_i2 = (const float*)d_in[24];

    const int KW = 372226, AU = 19065, MG = 28028, TG = 86037;

    BigParams bp;
    bp.A[0] = kw;  bp.A[1] = fo;  bp.A[2] = au;  bp.A[3] = mg;  bp.A[4] = tg;
    bp.W[0] = W_kw; bp.W[1] = W_au; bp.W[2] = W_au; bp.W[3] = W_mg; bp.W[4] = W_tg;
    bp.K[0] = KW;  bp.K[1] = AU;  bp.K[2] = AU;  bp.K[3] = MG;  bp.K[4] = TG;
    bp.kc[0] = 7168;   // 52*7168 = 372736
    bp.kc[1] = 6400;
    bp.kc[2] = 6400;
    bp.kc[3] = 7040;
    bp.kc[4] = 7232;
    bp.cum[0] = 0;
    bp.cum[1] = NSL_KW;
    bp.cum[2] = NSL_KW + NSL_FO;
    bp.cum[3] = NSL_KW + NSL_FO + NSL_AU;
    bp.cum[4] = NSL_KW + NSL_FO + NSL_AU + NSL_MG;
    bp.cum[5] = NSL_TOT;

    RedParams rp;
    rp.bias[0] = b_kw; rp.bias[1] = b_au; rp.bias[2] = b_au;
    rp.bias[3] = b_mg; rp.bias[4] = b_tg;
    for (int i = 0; i < 6; i++) rp.cum[i] = bp.cum[i];
    rp.col_ofs[0] = 0;   rp.col_ofs[1] = 128; rp.col_ofs[2] = 256;
    rp.col_ofs[3] = 384; rp.col_ofs[4] = 512;

    cudaFuncSetAttribute(big_gemm_kernel,
                         cudaFuncAttributeMaxDynamicSharedMemorySize, SMEM_DYN);

    big_gemm_kernel<<<NSL_TOT * 2, 512, SMEM_DYN>>>(bp);
    reduce_kernel<<<dim3((BATCH * EDIM) / 256, 5), 256>>>(rp);
    stats_kernel<<<NCOLS / 32, 256>>>(g_u, be_u, g_i, be_i);

    tower_kernel<<<BATCH / 8, 256>>>(0, 0,   256, W_u1, b_u1, 1, 1, 0);
    tower_kernel<<<BATCH / 8, 256>>>(1, 0,   128, W_u2, b_u2, 0, 0, 1);
    tower_kernel<<<BATCH / 8, 256>>>(0, 256, 384, W_i1, b_i1, 1, 1, 2);
    tower_kernel<<<BATCH / 8, 256>>>(2, 0,   128, W_i2, b_i2, 0, 0, 3);

    dot_kernel<<<BATCH / 8, 256>>>((float*)d_out);
}

// round 7
// speedup vs baseline: 5.9504x; 1.0007x over previous
#include <cuda_runtime.h>
#include <cuda_fp16.h>
#include <cstdint>

// ---------------- problem constants ----------------
#define BATCH 512
#define EDIM  128
#define NCOLS 640
#define EPS   1e-5f

// split-K: 74 slices, 2 row halves -> 148 CTAs (one wave)
#define NSL_KW 52
#define NSL_FO 3
#define NSL_AU 3
#define NSL_MG 4
#define NSL_TG 12
#define NSL_TOT (NSL_KW + NSL_FO + NSL_AU + NSL_MG + NSL_TG)   // 74

#define CH 32                  // K elements per chunk
#define OFS_WHI 16384          // W_hi offset in stage
#define STAGE   24576          // A_hi 16K | W_hi 8K
#define SMEM_DYN (2 * STAGE + 128)

// ---------------- device scratch ----------------
__device__ float g_part[(long)NSL_TOT * BATCH * EDIM];   // ~19.4 MB
__device__ float g_emb[BATCH * NCOLS];
__device__ float g_scale[NCOLS];
__device__ float g_shift[NCOLS];
__device__ float g_hu[BATCH * EDIM];
__device__ float g_ue[BATCH * EDIM];
__device__ float g_hi_[BATCH * EDIM];
__device__ float g_ie[BATCH * EDIM];

// ---------------- helpers ----------------
__device__ __forceinline__ uint32_t smem_u32(const void* p) {
    uint32_t a;
    asm("{ .reg .u64 t; cvta.to.shared.u64 t, %1; cvt.u32.u64 %0, t; }" : "=r"(a) : "l"(p));
    return a;
}

// swizzled byte offset: row r (64B wide), 16B chunk c (0..3)
__device__ __forceinline__ uint32_t swz(int r, int c) {
    return (uint32_t)r * 64u + (uint32_t)((c ^ ((r >> 1) & 3)) << 4);
}

#define LDX4(r, addr) \
    asm volatile("ldmatrix.sync.aligned.m8n8.x4.shared.b16 {%0,%1,%2,%3}, [%4];" \
        : "=r"((r)[0]), "=r"((r)[1]), "=r"((r)[2]), "=r"((r)[3]) : "r"(addr))

#define MMAF16(c, a, b) \
    asm volatile("mma.sync.aligned.m16n8k16.row.col.f32.f16.f16.f32 " \
        "{%0,%1,%2,%3}, {%4,%5,%6,%7}, {%8,%9}, {%0,%1,%2,%3};" \
        : "+f"((c)[0]), "+f"((c)[1]), "+f"((c)[2]), "+f"((c)[3]) \
        : "r"((a)[0]), "r"((a)[1]), "r"((a)[2]), "r"((a)[3]), \
          "r"((b)[0]), "r"((b)[1]))

#define STS128(addr, r) \
    asm volatile("st.shared.v4.b32 [%0], {%1,%2,%3,%4};" \
        :: "r"(addr), "r"((r)[0]), "r"((r)[1]), "r"((r)[2]), "r"((r)[3]) : "memory")

// 8 floats -> 4x fp16x2
__device__ __forceinline__ void cvt8(const float* x, uint32_t* hi) {
    #pragma unroll
    for (int q = 0; q < 4; q++) {
        __half2 h = __floats2half2_rn(x[2 * q], x[2 * q + 1]);
        hi[q] = *reinterpret_cast<uint32_t*>(&h);
    }
}

struct BigParams {
    const float* A[5];
    const float* W[5];
    int K[5];
    int kc[5];
    int cum[6];
};
struct RedParams {
    const float* bias[5];
    int cum[6];
    int col_ofs[5];
};

// ================= fp16 single-term mma.sync big GEMM =================
// CTA: 256 rows x one K-slice. 16 warps, warp tile 32m x 64n.
__global__ __launch_bounds__(512, 1) void big_gemm_kernel(BigParams p) {
    extern __shared__ __align__(128) char dyn_smem[];
    const uint32_t sBase = (smem_u32(dyn_smem) + 127u) & ~127u;

    const int t    = threadIdx.x;
    const int lane = t & 31;
    const int w    = t >> 5;

    const int sidx   = blockIdx.x >> 1;
    const int m_base = (blockIdx.x & 1) * 256;

    int g = 0;
    while (sidx >= p.cum[g + 1]) g++;
    const int s_loc = sidx - p.cum[g];
    const float* __restrict__ A = p.A[g];
    const float* __restrict__ W = p.W[g];
    const int K  = p.K[g];
    const int k0 = s_loc * p.kc[g];
    const int k1 = min(k0 + p.kc[g], K);
    const int nchunks = (k1 - k0 + CH - 1) / CH;
    const int kmode = ((K & 3) == 0) ? 2 : (((K & 1) == 0) ? 1 : 0);

    // load tasks: A rows lr and 128+lr; W row lr; 8k chunk lc
    const int lr  = t >> 2;
    const int lc  = t & 3;
    float aBuf[2][8], wBuf[8];

    // mma mapping
    const int wm = w >> 1;
    const int wn = w & 1;
    const int aR = wm * 32 + (lane & 15);
    const int bR = wn * 64 + ((lane >> 4) & 1) * 8 + (lane & 7);
    const int aCsel = (lane >> 4);        // 0/1
    const int bCsel = ((lane >> 3) & 1);  // 0/1

    float acc[2][4][2][4];
    #pragma unroll
    for (int mi = 0; mi < 2; mi++)
        #pragma unroll
        for (int np = 0; np < 4; np++)
            #pragma unroll
            for (int nt = 0; nt < 2; nt++)
                #pragma unroll
                for (int r = 0; r < 4; r++) acc[mi][np][nt][r] = 0.f;

    #define LOAD8(dst, P, gi, kk)                                             \
    do {                                                                      \
        if (full) {                                                           \
            if (kmode == 2) {                                                 \
                float4 v0 = *(const float4*)&P[gi];                           \
                float4 v1 = *(const float4*)&P[gi + 4];                       \
                dst[0]=v0.x; dst[1]=v0.y; dst[2]=v0.z; dst[3]=v0.w;           \
                dst[4]=v1.x; dst[5]=v1.y; dst[6]=v1.z; dst[7]=v1.w;           \
            } else if (kmode == 1) {                                          \
                _Pragma("unroll")                                             \
                for (int q = 0; q < 4; q++) {                                 \
                    float2 v = *(const float2*)&P[gi + 2 * q];                \
                    dst[2 * q] = v.x; dst[2 * q + 1] = v.y;                   \
                }                                                             \
            } else {                                                          \
                _Pragma("unroll")                                             \
                for (int q = 0; q < 8; q++) dst[q] = P[gi + q];               \
            }                                                                 \
        } else {                                                              \
            _Pragma("unroll")                                                 \
            for (int q = 0; q < 8; q++)                                       \
                dst[q] = (kk + q < k1) ? P[gi + q] : 0.f;                     \
        }                                                                     \
    } while (0)

    #define LOAD_CHUNK(IDX)                                                   \
    do {                                                                      \
        const int kb = k0 + (IDX) * CH;                                       \
        const bool full = (kb + CH <= k1);                                    \
        const int kk = kb + lc * 8;                                           \
        {                                                                     \
            long gi = (long)(m_base + lr) * K + kk;                           \
            LOAD8(aBuf[0], A, gi, kk);                                        \
        }                                                                     \
        {                                                                     \
            long gi = (long)(m_base + 128 + lr) * K + kk;                     \
            LOAD8(aBuf[1], A, gi, kk);                                        \
        }                                                                     \
        {                                                                     \
            long gi = (long)lr * K + kk;                                      \
            LOAD8(wBuf, W, gi, kk);                                           \
        }                                                                     \
    } while (0)

    #define STS_CHUNK(SO)                                                     \
    do {                                                                      \
        const uint32_t so = sBase + (SO);                                     \
        uint32_t hi[4];                                                       \
        uint32_t off0 = swz(lr, lc);                                          \
        cvt8(aBuf[0], hi);                                                    \
        STS128(so + off0, hi);                                                \
        cvt8(aBuf[1], hi);                                                    \
        STS128(so + swz(128 + lr, lc), hi);                                   \
        cvt8(wBuf, hi);                                                       \
        STS128(so + OFS_WHI + off0, hi);                                      \
    } while (0)

    LOAD_CHUNK(0);
    STS_CHUNK(0);
    __syncthreads();

    for (int i = 0; i < nchunks; i++) {
        const bool more = (i + 1 < nchunks);
        if (more) LOAD_CHUNK(i + 1);

        {
            const uint32_t so = sBase + (uint32_t)(i & 1) * STAGE;
            #pragma unroll
            for (int ks = 0; ks < 2; ks++) {
                uint32_t AH[2][4];
                #pragma unroll
                for (int mi = 0; mi < 2; mi++) {
                    int r = aR + mi * 16;
                    LDX4(AH[mi], so + swz(r, ks * 2 + aCsel));
                }
                #pragma unroll
                for (int np = 0; np < 4; np++) {
                    int r = bR + np * 16;
                    uint32_t BH[4];
                    LDX4(BH, so + OFS_WHI + swz(r, ks * 2 + bCsel));
                    #pragma unroll
                    for (int mi = 0; mi < 2; mi++) {
                        #pragma unroll
                        for (int nt = 0; nt < 2; nt++) {
                            MMAF16(acc[mi][np][nt], AH[mi], BH + 2 * nt);
                        }
                    }
                }
            }
        }

        if (more) STS_CHUNK((uint32_t)((i + 1) & 1) * STAGE);
        __syncthreads();
    }

    // epilogue
    #pragma unroll
    for (int mi = 0; mi < 2; mi++) {
        #pragma unroll
        for (int np = 0; np < 4; np++) {
            #pragma unroll
            for (int nt = 0; nt < 2; nt++) {
                int m = m_base + wm * 32 + mi * 16 + (lane >> 2);
                int n = wn * 64 + np * 16 + nt * 8 + (lane & 3) * 2;
                float* o = g_part + ((long)sidx * BATCH + m) * EDIM + n;
                *(float2*)o = make_float2(acc[mi][np][nt][0], acc[mi][np][nt][1]);
                *(float2*)(o + 8 * EDIM) = make_float2(acc[mi][np][nt][2], acc[mi][np][nt][3]);
            }
        }
    }
}

// ================= reduce split-K partials + bias =================
__global__ void reduce_kernel(RedParams p) {
    int g   = blockIdx.y;
    int idx = blockIdx.x * blockDim.x + threadIdx.x;
    int b   = idx >> 7;
    int j   = idx & 127;
    float v = p.bias[g][j];
    int s0 = p.cum[g], s1 = p.cum[g + 1];
    for (int s = s0; s < s1; s++)
        v += g_part[(long)s * (BATCH * EDIM) + idx];
    g_emb[b * NCOLS + p.col_ofs[g] + j] = v;
}

// ================= BN stats (coalesced) =================
__global__ void stats_kernel(const float* g_u, const float* be_u,
                             const float* g_i, const float* be_i) {
    __shared__ float ss[8][32], sq[8][32];
    int lane = threadIdx.x & 31;
    int ty   = threadIdx.x >> 5;
    int c = blockIdx.x * 32 + lane;
    float s = 0.f, q = 0.f;
    for (int b = ty; b < BATCH; b += 8) {
        float x = g_emb[b * NCOLS + c];
        s += x; q += x * x;
    }
    ss[ty][lane] = s; sq[ty][lane] = q;
    __syncthreads();
    if (ty == 0) {
        #pragma unroll
        for (int r = 1; r < 8; r++) { s += ss[r][lane]; q += sq[r][lane]; }
        float mean = s * (1.f / BATCH);
        float var  = q * (1.f / BATCH) - mean * mean;
        float gamma = (c < 256) ? g_u[c]  : g_i[c - 256];
        float beta  = (c < 256) ? be_u[c] : be_i[c - 256];
        float sc = gamma * rsqrtf(var + EPS);
        g_scale[c] = sc;
        g_shift[c] = beta - mean * sc;
    }
}

// ================= tower layer (smem-tiled W) =================
__global__ __launch_bounds__(256) void tower_kernel(
    int a_sel, int a_ofs, int K,
    const float* __restrict__ W, const float* __restrict__ bias,
    int use_norm, int do_relu, int c_sel) {

    __shared__ float As[8 * 384];
    __shared__ float Ws[32 * 128];

    const float* A; int lda;
    if (a_sel == 0)      { A = g_emb + a_ofs; lda = NCOLS; }
    else if (a_sel == 1) { A = g_hu;          lda = EDIM;  }
    else                 { A = g_hi_;         lda = EDIM;  }
    float* C = (c_sel == 0) ? g_hu : (c_sel == 1) ? g_ue
             : (c_sel == 2) ? g_hi_ : g_ie;

    int t  = threadIdx.x;
    int m0 = blockIdx.x * 8;

    for (int e = t; e < 8 * K; e += 256) {
        int r = e / K, c = e - r * K;
        float v = A[(m0 + r) * lda + c];
        if (use_norm) v = fmaf(v, g_scale[a_ofs + c], g_shift[a_ofs + c]);
        As[e] = v;
    }

    int r  = t >> 5;
    int j0 = (t & 31) * 4;
    float acc[4];
    #pragma unroll
    for (int j = 0; j < 4; j++) acc[j] = bias[j0 + j];

    int jw = t >> 1;
    int kh = (t & 1) * 16;
    for (int kb = 0; kb < K; kb += 32) {
        __syncthreads();
        #pragma unroll
        for (int q = 0; q < 4; q++) {
            float4 v = *(const float4*)&W[jw * K + kb + kh + q * 4];
            Ws[(kh + q * 4 + 0) * 128 + jw] = v.x;
            Ws[(kh + q * 4 + 1) * 128 + jw] = v.y;
            Ws[(kh + q * 4 + 2) * 128 + jw] = v.z;
            Ws[(kh + q * 4 + 3) * 128 + jw] = v.w;
        }
        __syncthreads();
        #pragma unroll 8
        for (int kk = 0; kk < 32; kk++) {
            float a = As[r * K + kb + kk];
            float4 wv = *(const float4*)&Ws[kk * 128 + j0];
            acc[0] = fmaf(a, wv.x, acc[0]);
            acc[1] = fmaf(a, wv.y, acc[1]);
            acc[2] = fmaf(a, wv.z, acc[2]);
            acc[3] = fmaf(a, wv.w, acc[3]);
        }
    }

    float4 v;
    v.x = do_relu ? fmaxf(acc[0], 0.f) : acc[0];
    v.y = do_relu ? fmaxf(acc[1], 0.f) : acc[1];
    v.z = do_relu ? fmaxf(acc[2], 0.f) : acc[2];
    v.w = do_relu ? fmaxf(acc[3], 0.f) : acc[3];
    *(float4*)&C[(m0 + r) * EDIM + j0] = v;
}

// ================= final dot =================
__global__ void dot_kernel(float* __restrict__ out) {
    int warp = threadIdx.x >> 5;
    int lane = threadIdx.x & 31;
    int b = blockIdx.x * 8 + warp;
    float s = 0.f;
    #pragma unroll
    for (int j = lane; j < EDIM; j += 32)
        s += g_ue[b * EDIM + j] * g_ie[b * EDIM + j];
    #pragma unroll
    for (int o = 16; o > 0; o >>= 1)
        s += __shfl_xor_sync(0xffffffffu, s, o);
    if (lane == 0) out[b] = s;
}

// ================= launch =================
extern "C" void kernel_launch(void* const* d_in, const int* in_sizes, int n_in,
                              void* d_out, int out_size) {
    const float* kw   = (const float*)d_in[0];
    const float* fo   = (const float*)d_in[1];
    const float* au   = (const float*)d_in[2];
    const float* mg   = (const float*)d_in[3];
    const float* tg   = (const float*)d_in[4];
    const float* W_kw = (const float*)d_in[5];
    const float* b_kw = (const float*)d_in[6];
    const float* W_au = (const float*)d_in[7];
    const float* b_au = (const float*)d_in[8];
    const float* W_mg = (const float*)d_in[9];
    const float* b_mg = (const float*)d_in[10];
    const float* W_tg = (const float*)d_in[11];
    const float* b_tg = (const float*)d_in[12];
    const float* g_u  = (const float*)d_in[13];
    const float* be_u = (const float*)d_in[14];
    const float* W_u1 = (const float*)d_in[15];
    const float* b_u1 = (const float*)d_in[16];
    const float* W_u2 = (const float*)d_in[17];
    const float* b_u2 = (const float*)d_in[18];
    const float* g_i  = (const float*)d_in[19];
    const float* be_i = (const float*)d_in[20];
    const float* W_i1 = (const float*)d_in[21];
    const float* b_i1 = (const float*)d_in[22];
    const float* W_i2 = (const float*)d_in[23];
    const float* b_i2 = (const float*)d_in[24];

    const int KW = 372226, AU = 19065, MG = 28028, TG = 86037;

    BigParams bp;
    bp.A[0] = kw;  bp.A[1] = fo;  bp.A[2] = au;  bp.A[3] = mg;  bp.A[4] = tg;
    bp.W[0] = W_kw; bp.W[1] = W_au; bp.W[2] = W_au; bp.W[3] = W_mg; bp.W[4] = W_tg;
    bp.K[0] = KW;  bp.K[1] = AU;  bp.K[2] = AU;  bp.K[3] = MG;  bp.K[4] = TG;
    bp.kc[0] = 7168;   // 52*7168 = 372736
    bp.kc[1] = 6400;
    bp.kc[2] = 6400;
    bp.kc[3] = 7040;
    bp.kc[4] = 7232;
    bp.cum[0] = 0;
    bp.cum[1] = NSL_KW;
    bp.cum[2] = NSL_KW + NSL_FO;
    bp.cum[3] = NSL_KW + NSL_FO + NSL_AU;
    bp.cum[4] = NSL_KW + NSL_FO + NSL_AU + NSL_MG;
    bp.cum[5] = NSL_TOT;

    RedParams rp;
    rp.bias[0] = b_kw; rp.bias[1] = b_au; rp.bias[2] = b_au;
    rp.bias[3] = b_mg; rp.bias[4] = b_tg;
    for (int i = 0; i < 6; i++) rp.cum[i] = bp.cum[i];
    rp.col_ofs[0] = 0;   rp.col_ofs[1] = 128; rp.col_ofs[2] = 256;
    rp.col_ofs[3] = 384; rp.col_ofs[4] = 512;

    cudaFuncSetAttribute(big_gemm_kernel,
                         cudaFuncAttributeMaxDynamicSharedMemorySize, SMEM_DYN);

    big_gemm_kernel<<<NSL_TOT * 2, 512, SMEM_DYN>>>(bp);
    reduce_kernel<<<dim3((BATCH * EDIM) / 256, 5), 256>>>(rp);
    stats_kernel<<<NCOLS / 32, 256>>>(g_u, be_u, g_i, be_i);

    tower_kernel<<<BATCH / 8, 256>>>(0, 0,   256, W_u1, b_u1, 1, 1, 0);
    tower_kernel<<<BATCH / 8, 256>>>(1, 0,   128, W_u2, b_u2, 0, 0, 1);
    tower_kernel<<<BATCH / 8, 256>>>(0, 256, 384, W_i1, b_i1, 1, 1, 2);
    tower_kernel<<<BATCH / 8, 256>>>(2, 0,   128, W_i2, b_i2, 0, 0, 3);

    dot_kernel<<<BATCH / 8, 256>>>((float*)d_out);
}

// round 8
// speedup vs baseline: 6.2605x; 1.0521x over previous
#include <cuda_runtime.h>
#include <cuda_fp16.h>
#include <cstdint>

// ---------------- problem constants ----------------
#define BATCH 512
#define EDIM  128
#define NCOLS 640
#define EPS   1e-5f

// split-K: 74 slices, 4 m-tiles of 128 rows -> 296 CTAs (2 per SM)
#define NSL_KW 52
#define NSL_FO 3
#define NSL_AU 3
#define NSL_MG 4
#define NSL_TG 12
#define NSL_TOT (NSL_KW + NSL_FO + NSL_AU + NSL_MG + NSL_TG)   // 74

#define CH 32                  // K elements per chunk
#define OFS_WHI 8192           // W offset in stage
#define STAGE   16384          // A 8K | W 8K
#define SMEM_DYN (2 * STAGE + 128)

// ---------------- device scratch ----------------
__device__ float g_part[(long)NSL_TOT * BATCH * EDIM];   // ~19.4 MB
__device__ float g_emb[BATCH * NCOLS];
__device__ float g_scale[NCOLS];
__device__ float g_shift[NCOLS];
__device__ float g_hu[BATCH * EDIM];
__device__ float g_ue[BATCH * EDIM];
__device__ float g_hi_[BATCH * EDIM];
__device__ float g_ie[BATCH * EDIM];

// ---------------- helpers ----------------
__device__ __forceinline__ uint32_t smem_u32(const void* p) {
    uint32_t a;
    asm("{ .reg .u64 t; cvta.to.shared.u64 t, %1; cvt.u32.u64 %0, t; }" : "=r"(a) : "l"(p));
    return a;
}

// swizzled byte offset: row r (64B wide), 16B chunk c (0..3)
__device__ __forceinline__ uint32_t swz(int r, int c) {
    return (uint32_t)r * 64u + (uint32_t)((c ^ ((r >> 1) & 3)) << 4);
}

#define LDX4(r, addr) \
    asm volatile("ldmatrix.sync.aligned.m8n8.x4.shared.b16 {%0,%1,%2,%3}, [%4];" \
        : "=r"((r)[0]), "=r"((r)[1]), "=r"((r)[2]), "=r"((r)[3]) : "r"(addr))

#define MMAF16(c, a, b) \
    asm volatile("mma.sync.aligned.m16n8k16.row.col.f32.f16.f16.f32 " \
        "{%0,%1,%2,%3}, {%4,%5,%6,%7}, {%8,%9}, {%0,%1,%2,%3};" \
        : "+f"((c)[0]), "+f"((c)[1]), "+f"((c)[2]), "+f"((c)[3]) \
        : "r"((a)[0]), "r"((a)[1]), "r"((a)[2]), "r"((a)[3]), \
          "r"((b)[0]), "r"((b)[1]))

#define STS128(addr, r) \
    asm volatile("st.shared.v4.b32 [%0], {%1,%2,%3,%4};" \
        :: "r"(addr), "r"((r)[0]), "r"((r)[1]), "r"((r)[2]), "r"((r)[3]) : "memory")

// 8 floats -> 4x fp16x2
__device__ __forceinline__ void cvt8(const float* x, uint32_t* hi) {
    #pragma unroll
    for (int q = 0; q < 4; q++) {
        __half2 h = __floats2half2_rn(x[2 * q], x[2 * q + 1]);
        hi[q] = *reinterpret_cast<uint32_t*>(&h);
    }
}

struct BigParams {
    const float* A[5];
    const float* W[5];
    int K[5];
    int kc[5];
    int cum[6];
};
struct RedParams {
    const float* bias[5];
    int cum[6];
    int col_ofs[5];
};
struct TowerParams {
    const float* W[2];
    const float* bias[2];
};

// ================= fp16 mma.sync big GEMM, 2 CTAs/SM =================
// CTA: 128 rows x one K-slice. 8 warps, warp tile 32m x 64n.
__global__ __launch_bounds__(256, 2) void big_gemm_kernel(BigParams p) {
    extern __shared__ __align__(128) char dyn_smem[];
    const uint32_t sBase = (smem_u32(dyn_smem) + 127u) & ~127u;

    const int t    = threadIdx.x;
    const int lane = t & 31;
    const int w    = t >> 5;

    const int sidx   = blockIdx.x >> 2;
    const int m_base = (blockIdx.x & 3) * 128;

    int g = 0;
    while (sidx >= p.cum[g + 1]) g++;
    const int s_loc = sidx - p.cum[g];
    const float* __restrict__ A = p.A[g];
    const float* __restrict__ W = p.W[g];
    const int K  = p.K[g];
    const int k0 = s_loc * p.kc[g];
    const int k1 = min(k0 + p.kc[g], K);
    const int nchunks = (k1 - k0 + CH - 1) / CH;
    const int kmode = ((K & 3) == 0) ? 2 : (((K & 1) == 0) ? 1 : 0);

    // load tasks: A rows lr, 64+lr; W rows lr, 64+lr; 8k chunk lc
    const int lr  = t >> 2;      // 0..63
    const int lc  = t & 3;
    float aBuf[2][8], wBuf[2][8];

    // mma mapping (8 warps: 4 wm x 2 wn)
    const int wm = w >> 1;
    const int wn = w & 1;
    const int aR = wm * 32 + (lane & 15);
    const int bR = wn * 64 + ((lane >> 4) & 1) * 8 + (lane & 7);
    const int aCsel = (lane >> 4);        // 0/1
    const int bCsel = ((lane >> 3) & 1);  // 0/1

    float acc[2][4][2][4];
    #pragma unroll
    for (int mi = 0; mi < 2; mi++)
        #pragma unroll
        for (int np = 0; np < 4; np++)
            #pragma unroll
            for (int nt = 0; nt < 2; nt++)
                #pragma unroll
                for (int r = 0; r < 4; r++) acc[mi][np][nt][r] = 0.f;

    #define LOAD8(dst, P, gi, kk)                                             \
    do {                                                                      \
        if (full) {                                                           \
            if (kmode == 2) {                                                 \
                float4 v0 = *(const float4*)&P[gi];                           \
                float4 v1 = *(const float4*)&P[gi + 4];                       \
                dst[0]=v0.x; dst[1]=v0.y; dst[2]=v0.z; dst[3]=v0.w;           \
                dst[4]=v1.x; dst[5]=v1.y; dst[6]=v1.z; dst[7]=v1.w;           \
            } else if (kmode == 1) {                                          \
                _Pragma("unroll")                                             \
                for (int q = 0; q < 4; q++) {                                 \
                    float2 v = *(const float2*)&P[gi + 2 * q];                \
                    dst[2 * q] = v.x; dst[2 * q + 1] = v.y;                   \
                }                                                             \
            } else {                                                          \
                _Pragma("unroll")                                             \
                for (int q = 0; q < 8; q++) dst[q] = P[gi + q];               \
            }                                                                 \
        } else {                                                              \
            _Pragma("unroll")                                                 \
            for (int q = 0; q < 8; q++)                                       \
                dst[q] = (kk + q < k1) ? P[gi + q] : 0.f;                     \
        }                                                                     \
    } while (0)

    #define LOAD_CHUNK(IDX)                                                   \
    do {                                                                      \
        const int kb = k0 + (IDX) * CH;                                       \
        const bool full = (kb + CH <= k1);                                    \
        const int kk = kb + lc * 8;                                           \
        { long gi = (long)(m_base + lr) * K + kk;      LOAD8(aBuf[0], A, gi, kk); } \
        { long gi = (long)(m_base + 64 + lr) * K + kk; LOAD8(aBuf[1], A, gi, kk); } \
        { long gi = (long)lr * K + kk;                 LOAD8(wBuf[0], W, gi, kk); } \
        { long gi = (long)(64 + lr) * K + kk;          LOAD8(wBuf[1], W, gi, kk); } \
    } while (0)

    #define STS_CHUNK(SO)                                                     \
    do {                                                                      \
        const uint32_t so = sBase + (SO);                                     \
        uint32_t hi[4];                                                       \
        uint32_t off0 = swz(lr, lc);                                          \
        uint32_t off1 = swz(64 + lr, lc);                                     \
        cvt8(aBuf[0], hi);  STS128(so + off0, hi);                            \
        cvt8(aBuf[1], hi);  STS128(so + off1, hi);                            \
        cvt8(wBuf[0], hi);  STS128(so + OFS_WHI + off0, hi);                  \
        cvt8(wBuf[1], hi);  STS128(so + OFS_WHI + off1, hi);                  \
    } while (0)

    LOAD_CHUNK(0);
    STS_CHUNK(0);
    __syncthreads();

    for (int i = 0; i < nchunks; i++) {
        const bool more = (i + 1 < nchunks);
        if (more) LOAD_CHUNK(i + 1);

        {
            const uint32_t so = sBase + (uint32_t)(i & 1) * STAGE;
            #pragma unroll
            for (int ks = 0; ks < 2; ks++) {
                uint32_t AH[2][4];
                #pragma unroll
                for (int mi = 0; mi < 2; mi++) {
                    int r = aR + mi * 16;
                    LDX4(AH[mi], so + swz(r, ks * 2 + aCsel));
                }
                #pragma unroll
                for (int np = 0; np < 4; np++) {
                    int r = bR + np * 16;
                    uint32_t BH[4];
                    LDX4(BH, so + OFS_WHI + swz(r, ks * 2 + bCsel));
                    #pragma unroll
                    for (int mi = 0; mi < 2; mi++) {
                        #pragma unroll
                        for (int nt = 0; nt < 2; nt++) {
                            MMAF16(acc[mi][np][nt], AH[mi], BH + 2 * nt);
                        }
                    }
                }
            }
        }

        if (more) STS_CHUNK((uint32_t)((i + 1) & 1) * STAGE);
        __syncthreads();
    }

    // epilogue
    #pragma unroll
    for (int mi = 0; mi < 2; mi++) {
        #pragma unroll
        for (int np = 0; np < 4; np++) {
            #pragma unroll
            for (int nt = 0; nt < 2; nt++) {
                int m = m_base + wm * 32 + mi * 16 + (lane >> 2);
                int n = wn * 64 + np * 16 + nt * 8 + (lane & 3) * 2;
                float* o = g_part + ((long)sidx * BATCH + m) * EDIM + n;
                *(float2*)o = make_float2(acc[mi][np][nt][0], acc[mi][np][nt][1]);
                *(float2*)(o + 8 * EDIM) = make_float2(acc[mi][np][nt][2], acc[mi][np][nt][3]);
            }
        }
    }
}

// ================= reduce split-K partials + bias =================
__global__ void reduce_kernel(RedParams p) {
    int g   = blockIdx.y;
    int idx = blockIdx.x * blockDim.x + threadIdx.x;
    int b   = idx >> 7;
    int j   = idx & 127;
    float v = p.bias[g][j];
    int s0 = p.cum[g], s1 = p.cum[g + 1];
    for (int s = s0; s < s1; s++)
        v += g_part[(long)s * (BATCH * EDIM) + idx];
    g_emb[b * NCOLS + p.col_ofs[g] + j] = v;
}

// ================= BN stats (coalesced) =================
__global__ void stats_kernel(const float* g_u, const float* be_u,
                             const float* g_i, const float* be_i) {
    __shared__ float ss[8][32], sq[8][32];
    int lane = threadIdx.x & 31;
    int ty   = threadIdx.x >> 5;
    int c = blockIdx.x * 32 + lane;
    float s = 0.f, q = 0.f;
    for (int b = ty; b < BATCH; b += 8) {
        float x = g_emb[b * NCOLS + c];
        s += x; q += x * x;
    }
    ss[ty][lane] = s; sq[ty][lane] = q;
    __syncthreads();
    if (ty == 0) {
        #pragma unroll
        for (int r = 1; r < 8; r++) { s += ss[r][lane]; q += sq[r][lane]; }
        float mean = s * (1.f / BATCH);
        float var  = q * (1.f / BATCH) - mean * mean;
        float gamma = (c < 256) ? g_u[c]  : g_i[c - 256];
        float beta  = (c < 256) ? be_u[c] : be_i[c - 256];
        float sc = gamma * rsqrtf(var + EPS);
        g_scale[c] = sc;
        g_shift[c] = beta - mean * sc;
    }
}

// ================= fused tower layer 1 (user + item) =================
__global__ __launch_bounds__(256) void tower1_kernel(TowerParams p) {
    __shared__ float As[8 * 384];
    __shared__ float Ws[32 * 128];

    int which = blockIdx.x >> 6;          // 0 = user, 1 = item
    int blk   = blockIdx.x & 63;
    int K     = which ? 384 : 256;
    int a_ofs = which ? 256 : 0;
    const float* __restrict__ W    = p.W[which];
    const float* __restrict__ bias = p.bias[which];
    float* C = which ? g_hi_ : g_hu;

    int t  = threadIdx.x;
    int m0 = blk * 8;

    for (int e = t; e < 8 * K; e += 256) {
        int r = e / K, c = e - r * K;
        float v = g_emb[(m0 + r) * NCOLS + a_ofs + c];
        As[e] = fmaf(v, g_scale[a_ofs + c], g_shift[a_ofs + c]);
    }

    int r  = t >> 5;
    int j0 = (t & 31) * 4;
    float acc[4];
    #pragma unroll
    for (int j = 0; j < 4; j++) acc[j] = bias[j0 + j];

    int jw = t >> 1;
    int kh = (t & 1) * 16;
    for (int kb = 0; kb < K; kb += 32) {
        __syncthreads();
        #pragma unroll
        for (int q = 0; q < 4; q++) {
            float4 v = *(const float4*)&W[jw * K + kb + kh + q * 4];
            Ws[(kh + q * 4 + 0) * 128 + jw] = v.x;
            Ws[(kh + q * 4 + 1) * 128 + jw] = v.y;
            Ws[(kh + q * 4 + 2) * 128 + jw] = v.z;
            Ws[(kh + q * 4 + 3) * 128 + jw] = v.w;
        }
        __syncthreads();
        #pragma unroll 8
        for (int kk = 0; kk < 32; kk++) {
            float a = As[r * K + kb + kk];
            float4 wv = *(const float4*)&Ws[kk * 128 + j0];
            acc[0] = fmaf(a, wv.x, acc[0]);
            acc[1] = fmaf(a, wv.y, acc[1]);
            acc[2] = fmaf(a, wv.z, acc[2]);
            acc[3] = fmaf(a, wv.w, acc[3]);
        }
    }

    float4 v;
    v.x = fmaxf(acc[0], 0.f);
    v.y = fmaxf(acc[1], 0.f);
    v.z = fmaxf(acc[2], 0.f);
    v.w = fmaxf(acc[3], 0.f);
    *(float4*)&C[(m0 + r) * EDIM + j0] = v;
}

// ================= fused tower layer 2 (user + item) =================
__global__ __launch_bounds__(256) void tower2_kernel(TowerParams p) {
    __shared__ float As[8 * 128];
    __shared__ float Ws[32 * 128];

    int which = blockIdx.x >> 6;
    int blk   = blockIdx.x & 63;
    const int K = 128;
    const float* __restrict__ A    = which ? g_hi_ : g_hu;
    const float* __restrict__ W    = p.W[which];
    const float* __restrict__ bias = p.bias[which];
    float* C = which ? g_ie : g_ue;

    int t  = threadIdx.x;
    int m0 = blk * 8;

    for (int e = t; e < 8 * K; e += 256) As[e] = A[m0 * K + e];

    int r  = t >> 5;
    int j0 = (t & 31) * 4;
    float acc[4];
    #pragma unroll
    for (int j = 0; j < 4; j++) acc[j] = bias[j0 + j];

    int jw = t >> 1;
    int kh = (t & 1) * 16;
    for (int kb = 0; kb < K; kb += 32) {
        __syncthreads();
        #pragma unroll
        for (int q = 0; q < 4; q++) {
            float4 v = *(const float4*)&W[jw * K + kb + kh + q * 4];
            Ws[(kh + q * 4 + 0) * 128 + jw] = v.x;
            Ws[(kh + q * 4 + 1) * 128 + jw] = v.y;
            Ws[(kh + q * 4 + 2) * 128 + jw] = v.z;
            Ws[(kh + q * 4 + 3) * 128 + jw] = v.w;
        }
        __syncthreads();
        #pragma unroll 8
        for (int kk = 0; kk < 32; kk++) {
            float a = As[r * K + kb + kk];
            float4 wv = *(const float4*)&Ws[kk * 128 + j0];
            acc[0] = fmaf(a, wv.x, acc[0]);
            acc[1] = fmaf(a, wv.y, acc[1]);
            acc[2] = fmaf(a, wv.z, acc[2]);
            acc[3] = fmaf(a, wv.w, acc[3]);
        }
    }

    *(float4*)&C[(m0 + r) * EDIM + j0] =
        make_float4(acc[0], acc[1], acc[2], acc[3]);
}

// ================= final dot =================
__global__ void dot_kernel(float* __restrict__ out) {
    int warp = threadIdx.x >> 5;
    int lane = threadIdx.x & 31;
    int b = blockIdx.x * 8 + warp;
    float s = 0.f;
    #pragma unroll
    for (int j = lane; j < EDIM; j += 32)
        s += g_ue[b * EDIM + j] * g_ie[b * EDIM + j];
    #pragma unroll
    for (int o = 16; o > 0; o >>= 1)
        s += __shfl_xor_sync(0xffffffffu, s, o);
    if (lane == 0) out[b] = s;
}

// ================= launch =================
extern "C" void kernel_launch(void* const* d_in, const int* in_sizes, int n_in,
                              void* d_out, int out_size) {
    const float* kw   = (const float*)d_in[0];
    const float* fo   = (const float*)d_in[1];
    const float* au   = (const float*)d_in[2];
    const float* mg   = (const float*)d_in[3];
    const float* tg   = (const float*)d_in[4];
    const float* W_kw = (const float*)d_in[5];
    const float* b_kw = (const float*)d_in[6];
    const float* W_au = (const float*)d_in[7];
    const float* b_au = (const float*)d_in[8];
    const float* W_mg = (const float*)d_in[9];
    const float* b_mg = (const float*)d_in[10];
    const float* W_tg = (const float*)d_in[11];
    const float* b_tg = (const float*)d_in[12];
    const float* g_u  = (const float*)d_in[13];
    const float* be_u = (const float*)d_in[14];
    const float* W_u1 = (const float*)d_in[15];
    const float* b_u1 = (const float*)d_in[16];
    const float* W_u2 = (const float*)d_in[17];
    const float* b_u2 = (const float*)d_in[18];
    const float* g_i  = (const float*)d_in[19];
    const float* be_i = (const float*)d_in[20];
    const float* W_i1 = (const float*)d_in[21];
    const float* b_i1 = (const float*)d_in[22];
    const float* W_i2 = (const float*)d_in[23];
    const float* b_i2 = (const float*)d_in[24];

    const int KW = 372226, AU = 19065, MG = 28028, TG = 86037;

    BigParams bp;
    bp.A[0] = kw;  bp.A[1] = fo;  bp.A[2] = au;  bp.A[3] = mg;  bp.A[4] = tg;
    bp.W[0] = W_kw; bp.W[1] = W_au; bp.W[2] = W_au; bp.W[3] = W_mg; bp.W[4] = W_tg;
    bp.K[0] = KW;  bp.K[1] = AU;  bp.K[2] = AU;  bp.K[3] = MG;  bp.K[4] = TG;
    bp.kc[0] = 7168;   // 52*7168 = 372736
    bp.kc[1] = 6400;
    bp.kc[2] = 6400;
    bp.kc[3] = 7040;
    bp.kc[4] = 7232;
    bp.cum[0] = 0;
    bp.cum[1] = NSL_KW;
    bp.cum[2] = NSL_KW + NSL_FO;
    bp.cum[3] = NSL_KW + NSL_FO + NSL_AU;
    bp.cum[4] = NSL_KW + NSL_FO + NSL_AU + NSL_MG;
    bp.cum[5] = NSL_TOT;

    RedParams rp;
    rp.bias[0] = b_kw; rp.bias[1] = b_au; rp.bias[2] = b_au;
    rp.bias[3] = b_mg; rp.bias[4] = b_tg;
    for (int i = 0; i < 6; i++) rp.cum[i] = bp.cum[i];
    rp.col_ofs[0] = 0;   rp.col_ofs[1] = 128; rp.col_ofs[2] = 256;
    rp.col_ofs[3] = 384; rp.col_ofs[4] = 512;

    TowerParams t1;
    t1.W[0] = W_u1; t1.W[1] = W_i1;
    t1.bias[0] = b_u1; t1.bias[1] = b_i1;
    TowerParams t2;
    t2.W[0] = W_u2; t2.W[1] = W_i2;
    t2.bias[0] = b_u2; t2.bias[1] = b_i2;

    cudaFuncSetAttribute(big_gemm_kernel,
                         cudaFuncAttributeMaxDynamicSharedMemorySize, SMEM_DYN);

    big_gemm_kernel<<<NSL_TOT * 4, 256, SMEM_DYN>>>(bp);
    reduce_kernel<<<dim3((BATCH * EDIM) / 256, 5), 256>>>(rp);
    stats_kernel<<<NCOLS / 32, 256>>>(g_u, be_u, g_i, be_i);
    tower1_kernel<<<128, 256>>>(t1);
    tower2_kernel<<<128, 256>>>(t2);
    dot_kernel<<<BATCH / 8, 256>>>((float*)d_out);
}